// round 11
// baseline (speedup 1.0000x reference)
#include <cuda_runtime.h>
#include <cstdint>

// Problem: B=2, N=2048, C=1024, H=16, D=64
// g_q/g_k/g_v: [bh=32][n=2048][128], d 0..63 real, 64..127 imag (tf32-rounded)
// g_z: [b*2048+n][2048] = [out_r(1024) | out_i(1024)] (tf32-rounded)
// g_x, g_w: tf32-rounded copies of x and the 6 QKV weights
// g_wc, g_fb: combined output weight (tf32-rounded) and bias

#define PROJ_SMEM (2 * 2 * 128 * 36 * 4)                              // 73728 B
#define ATT_SMEM  ((2 * 32 * 132 + 2 * 32 * 136 + 2 * 64 * 36) * 4)   // 87040 B

__device__ float g_q[32 * 2048 * 128];
__device__ float g_k[32 * 2048 * 128];
__device__ float g_v[32 * 2048 * 128];
__device__ float g_z[4096 * 2048];
__device__ float g_x[4096 * 1024];
__device__ float g_w[6 * 1024 * 1024];
__device__ float g_wc[1024 * 2048];
__device__ float g_fb[1024];

// ---------------------------------------------------------------------------
// helpers
// ---------------------------------------------------------------------------
__device__ __forceinline__ float tf32f(float x) {
    uint32_t r;
    asm("cvt.rna.tf32.f32 %0, %1;" : "=r"(r) : "f"(x));
    return __int_as_float(r);
}
__device__ __forceinline__ uint32_t fu(float x) { return __float_as_uint(x); }

__device__ __forceinline__ float sqrt_ap(float x) {
    float r;
    asm("sqrt.approx.f32 %0, %1;" : "=f"(r) : "f"(x));
    return r;
}
__device__ __forceinline__ float ex2_ap(float x) {
    float r;
    asm("ex2.approx.f32 %0, %1;" : "=f"(r) : "f"(x));
    return r;
}

__device__ __forceinline__ void mma8(float* d,
                                     uint32_t a0, uint32_t a1, uint32_t a2, uint32_t a3,
                                     uint32_t b0, uint32_t b1) {
    asm volatile(
        "mma.sync.aligned.m16n8k8.row.col.f32.tf32.tf32.f32 "
        "{%0,%1,%2,%3}, {%4,%5,%6,%7}, {%8,%9}, {%0,%1,%2,%3};"
        : "+f"(d[0]), "+f"(d[1]), "+f"(d[2]), "+f"(d[3])
        : "r"(a0), "r"(a1), "r"(a2), "r"(a3), "r"(b0), "r"(b1));
}

__device__ __forceinline__ void cpa16(uint32_t dst, const float* src) {
    asm volatile("cp.async.cg.shared.global [%0], [%1], 16;" :: "r"(dst), "l"(src));
}
#define CP_COMMIT() asm volatile("cp.async.commit_group;")
#define CP_WAIT0()  asm volatile("cp.async.wait_group 0;")

// ---------------------------------------------------------------------------
// Pre-round x and the 6 QKV weights into g_x / g_w (tf32).
// ---------------------------------------------------------------------------
__global__ void __launch_bounds__(256) prep_kernel(
    const float* __restrict__ x,
    const float* __restrict__ qrw, const float* __restrict__ qiw,
    const float* __restrict__ krw, const float* __restrict__ kiw,
    const float* __restrict__ vrw, const float* __restrict__ viw)
{
    int i4 = blockIdx.x * 256 + threadIdx.x;
    const float* src;
    float* dst;
    if (i4 < 1048576) {
        src = x + (size_t)i4 * 4;
        dst = g_x + (size_t)i4 * 4;
    } else {
        int j = i4 - 1048576;
        int wsel = j >> 18;
        int off = j & 262143;
        const float* wp;
        switch (wsel) {
            case 0: wp = qrw; break;
            case 1: wp = qiw; break;
            case 2: wp = krw; break;
            case 3: wp = kiw; break;
            case 4: wp = vrw; break;
            default: wp = viw; break;
        }
        src = wp + (size_t)off * 4;
        dst = g_w + (size_t)wsel * 1048576 + (size_t)off * 4;
    }
    float4 v = *(const float4*)src;
    v.x = tf32f(v.x); v.y = tf32f(v.y); v.z = tf32f(v.z); v.w = tf32f(v.w);
    *(float4*)dst = v;
}

// ---------------------------------------------------------------------------
// Combined output weight (tf32-rounded) + bias.
// ---------------------------------------------------------------------------
__global__ void __launch_bounds__(256) make_wc_kernel(
    const float* __restrict__ orw, const float* __restrict__ oiw,
    const float* __restrict__ orb, const float* __restrict__ oib)
{
    int idx = blockIdx.x * 256 + threadIdx.x;
    int o = idx >> 9;
    int k = (idx & 511) << 2;
    float4 r;
    if (k < 1024) {
        float4 a = *(const float4*)(orw + (size_t)o * 1024 + k);
        float4 b = *(const float4*)(oiw + (size_t)o * 1024 + k);
        r.x = fmaf(0.1f, b.x, a.x); r.y = fmaf(0.1f, b.y, a.y);
        r.z = fmaf(0.1f, b.z, a.z); r.w = fmaf(0.1f, b.w, a.w);
    } else {
        int kk = k - 1024;
        float4 a = *(const float4*)(orw + (size_t)o * 1024 + kk);
        float4 b = *(const float4*)(oiw + (size_t)o * 1024 + kk);
        r.x = fmaf(0.1f, a.x, -b.x); r.y = fmaf(0.1f, a.y, -b.y);
        r.z = fmaf(0.1f, a.z, -b.z); r.w = fmaf(0.1f, a.w, -b.w);
    }
    r.x = tf32f(r.x); r.y = tf32f(r.y); r.z = tf32f(r.z); r.w = tf32f(r.w);
    *(float4*)(g_wc + (size_t)o * 2048 + k) = r;
    if ((idx & 511) == 0)
        g_fb[o] = 1.1f * orb[o] - 0.9f * oib[o];
}

// ---------------------------------------------------------------------------
// Input projections: blockIdx.z = 0/1/2 -> Q/K/V.
// BM=128, BN=128, BK=32, cp.async double-buffered smem, tf32 mma.
// ---------------------------------------------------------------------------
__global__ void __launch_bounds__(256, 2) proj_mma_kernel(
    const float* __restrict__ qrb, const float* __restrict__ qib,
    const float* __restrict__ krb, const float* __restrict__ kib,
    const float* __restrict__ vrb, const float* __restrict__ vib)
{
    extern __shared__ float sm[];
    float* As = sm;                 // [2][128][36]
    float* Bs = sm + 2 * 128 * 36;  // [2][128][36]
    const uint32_t as_u = (uint32_t)__cvta_generic_to_shared(As);
    const uint32_t bs_u = (uint32_t)__cvta_generic_to_shared(Bs);

    const int t = threadIdx.x;
    const int w = t >> 5, lane = t & 31, g = lane >> 2, tg = lane & 3;
    const int wm = w >> 2, wn = w & 3;
    const int z = blockIdx.z;
    const int bx = blockIdx.x;
    const int m0 = blockIdx.y * 128;
    const bool imag = bx >= 8;
    const float* bias;
    float* Out;
    if (z == 0)      { bias = imag ? qib : qrb; Out = g_q; }
    else if (z == 1) { bias = imag ? kib : krb; Out = g_k; }
    else             { bias = imag ? vib : vrb; Out = g_v; }
    const float* W = g_w + (size_t)(z * 2 + (imag ? 1 : 0)) * 1024 * 1024;
    const int o0 = (bx & 7) * 128;

    int lr[4], lc[4];
    #pragma unroll
    for (int i = 0; i < 4; i++) { int idx = i * 256 + t; lr[i] = idx >> 3; lc[i] = (idx & 7) * 4; }

    const float* Ag = g_x + (size_t)m0 * 1024;
    const float* Bg = W + (size_t)o0 * 1024;

    auto loadAB = [&](int k0, int buf) {
        const int boff = buf * 128 * 36;
        #pragma unroll
        for (int i = 0; i < 4; i++) {
            cpa16(as_u + (boff + lr[i] * 36 + lc[i]) * 4, Ag + lr[i] * 1024 + k0 + lc[i]);
            cpa16(bs_u + (boff + lr[i] * 36 + lc[i]) * 4, Bg + lr[i] * 1024 + k0 + lc[i]);
        }
        CP_COMMIT();
    };

    float acc[4][4][4];
    #pragma unroll
    for (int a = 0; a < 4; a++)
        #pragma unroll
        for (int b = 0; b < 4; b++)
            #pragma unroll
            for (int c = 0; c < 4; c++) acc[a][b][c] = 0.f;

    loadAB(0, 0);

    for (int kt = 0; kt < 32; kt++) {
        CP_WAIT0();
        __syncthreads();
        if (kt + 1 < 32) loadAB((kt + 1) * 32, (kt + 1) & 1);
        const float* Ab = As + (kt & 1) * 128 * 36;
        const float* Bb = Bs + (kt & 1) * 128 * 36;
        #pragma unroll
        for (int ks = 0; ks < 4; ks++) {
            const int col = 8 * ks + tg;
            uint32_t a[4][4];
            #pragma unroll
            for (int mt = 0; mt < 4; mt++) {
                const float* ap = Ab + (64 * wm + 16 * mt + g) * 36;
                a[mt][0] = fu(ap[col]);
                a[mt][1] = fu(ap[8 * 36 + col]);
                a[mt][2] = fu(ap[col + 4]);
                a[mt][3] = fu(ap[8 * 36 + col + 4]);
            }
            #pragma unroll
            for (int nt = 0; nt < 4; nt++) {
                const float* bp = Bb + (32 * wn + 8 * nt + g) * 36;
                uint32_t b0 = fu(bp[col]);
                uint32_t b1 = fu(bp[col + 4]);
                #pragma unroll
                for (int mt = 0; mt < 4; mt++)
                    mma8(acc[mt][nt], a[mt][0], a[mt][1], a[mt][2], a[mt][3], b0, b1);
            }
        }
    }

    // epilogue: scatter tf32-rounded (acc + bias) into [bh][n][128]
    const int part = imag ? 1 : 0;
    const int ob = o0 + 32 * wn;
    const int hh = ob >> 6;
    #pragma unroll
    for (int mt = 0; mt < 4; mt++) {
        int m = m0 + 64 * wm + 16 * mt + g;
        #pragma unroll
        for (int r = 0; r < 2; r++) {
            int mm = m + 8 * r;
            int b_ = mm >> 11, nn = mm & 2047;
            float* dst = Out + ((size_t)(b_ * 16 + hh) * 2048 + nn) * 128 + part * 64;
            #pragma unroll
            for (int nt = 0; nt < 4; nt++) {
                int o = ob + 8 * nt + 2 * tg;
                float2 bv = *(const float2*)(bias + o);
                *(float2*)(dst + (o & 63)) =
                    make_float2(tf32f(acc[mt][nt][2 * r + 0] + bv.x),
                                tf32f(acc[mt][nt][2 * r + 1] + bv.y));
            }
        }
    }
}

// ---------------------------------------------------------------------------
// Fused complex-magnitude attention, tf32 mma + MUFU softmax, DEFERRED PV.
// Block = 64 queries x one bh; 4 warps; 32-key tiles; 2 CTAs/SM (87KB smem).
// Iteration t: S-mma(t) -> PV-mma(t-1) -> softmax(t).
// PV(t-1) has no data deps in iter t, so it feeds the tensor pipe while
// softmax would otherwise stall on S(t) mma results. One wait+barrier/tile:
// top of iter t lands K(t) (issued t-1) and V(t-1) (issued t-1); then issue
// K(t+1) and V(t) (consumed at iter t+1 -> a full iteration of latency).
// P double-buffered. O accumulates tiles in identical order -> numerics
// bit-identical to the non-deferred version.
// ---------------------------------------------------------------------------
__global__ void __launch_bounds__(128, 2) attn_mma_kernel()
{
    extern __shared__ float sm[];
    float* Ks0 = sm;                   // [32][132]
    float* Ks1 = sm + 32 * 132;        // [32][132]
    float* Vs0 = sm + 2 * 32 * 132;    // [32][136]
    float* Vs1 = Vs0 + 32 * 136;       // [32][136]
    float* Ps0 = Vs1 + 32 * 136;       // [64][36]
    float* Ps1 = Ps0 + 64 * 36;        // [64][36]
    const uint32_t ks0_u = (uint32_t)__cvta_generic_to_shared(Ks0);
    const uint32_t ks1_u = (uint32_t)__cvta_generic_to_shared(Ks1);
    const uint32_t vs0_u = (uint32_t)__cvta_generic_to_shared(Vs0);
    const uint32_t vs1_u = (uint32_t)__cvta_generic_to_shared(Vs1);

    const int t = threadIdx.x;
    const int w = t >> 5, lane = t & 31, g = lane >> 2, tg = lane & 3;
    const int bh = blockIdx.y;
    const int q0 = blockIdx.x * 64;
    const int qrow = 16 * w;

    const float* Qg = g_q + ((size_t)bh * 2048 + q0) * 128;
    const float* Kg = g_k + (size_t)bh * 2048 * 128;
    const float* Vg = g_v + (size_t)bh * 2048 * 128;

    // stage Q (64 rows x 128, stride 132) through the K double-buffer area
    #pragma unroll
    for (int i = 0; i < 16; i++) {
        int idx = i * 128 + t;
        int row = idx >> 5, c4 = (idx & 31) * 4;
        cpa16(ks0_u + (row * 132 + c4) * 4, Qg + row * 128 + c4);
    }
    CP_COMMIT();
    CP_WAIT0();
    __syncthreads();

    // Q fragments -> registers
    float qr[8][4], qi[8][4];
    #pragma unroll
    for (int ks = 0; ks < 8; ks++) {
        const int col = 8 * ks + tg;
        const float* r0 = sm + (qrow + g) * 132;
        const float* r8 = sm + (qrow + g + 8) * 132;
        qr[ks][0] = r0[col];      qr[ks][1] = r8[col];
        qr[ks][2] = r0[col + 4];  qr[ks][3] = r8[col + 4];
        qi[ks][0] = r0[col + 64]; qi[ks][1] = r8[col + 64];
        qi[ks][2] = r0[col + 68]; qi[ks][3] = r8[col + 68];
    }
    __syncthreads();   // done reading staged Q before K(0) overwrites

    auto loadK = [&](int kt, uint32_t ku) {
        const float* Kt = Kg + (size_t)kt * 32 * 128;
        #pragma unroll
        for (int i = 0; i < 8; i++) {
            int idx = i * 128 + t;
            int row = idx >> 5, c4 = (idx & 31) * 4;
            cpa16(ku + (row * 132 + c4) * 4, Kt + row * 128 + c4);
        }
    };
    auto loadV = [&](int kt, uint32_t vu) {
        const float* Vt = Vg + (size_t)kt * 32 * 128;
        #pragma unroll
        for (int i = 0; i < 8; i++) {
            int idx = i * 128 + t;
            int row = idx >> 5, c4 = (idx & 31) * 4;
            cpa16(vu + (row * 136 + c4) * 4, Vt + row * 128 + c4);
        }
    };

    float O[16][4];
    #pragma unroll
    for (int i = 0; i < 16; i++) { O[i][0] = 0.f; O[i][1] = 0.f; O[i][2] = 0.f; O[i][3] = 0.f; }
    float l0 = 0.f, l1 = 0.f;

    const float K1 = 0.18033688f;   // 0.125 * log2(e)
    const float K2 = -11.541560f;   // -8 * log2(e)

    // O += P(pt) @ [vr|vi](pt)
    auto doPV = [&](int pt) {
        const float* Pb = (pt & 1) ? Ps1 : Ps0;
        const float* Vb = (pt & 1) ? Vs1 : Vs0;
        #pragma unroll
        for (int ks = 0; ks < 4; ks++) {
            const int pcol = 8 * ks + tg;
            uint32_t a0 = fu(Pb[(qrow + g) * 36 + pcol]);
            uint32_t a1 = fu(Pb[(qrow + g + 8) * 36 + pcol]);
            uint32_t a2 = fu(Pb[(qrow + g) * 36 + pcol + 4]);
            uint32_t a3 = fu(Pb[(qrow + g + 8) * 36 + pcol + 4]);
            const float* v0p = Vb + (8 * ks + tg) * 136 + g;
            const float* v1p = Vb + (8 * ks + tg + 4) * 136 + g;
            #pragma unroll
            for (int nt = 0; nt < 16; nt++) {
                uint32_t b0 = fu(v0p[8 * nt]);
                uint32_t b1 = fu(v1p[8 * nt]);
                mma8(O[nt], a0, a1, a2, a3, b0, b1);
            }
        }
    };

    loadK(0, ks0_u);
    CP_COMMIT();

    for (int kt = 0; kt < 64; kt++) {
        // lands: K(kt) (issued last iter) and V(kt-1) (issued last iter).
        CP_WAIT0();
        __syncthreads();
        // issue K(kt+1) and V(kt); V(kt) is consumed at iter kt+1.
        if (kt + 1 < 64) loadK(kt + 1, (kt & 1) ? ks0_u : ks1_u);
        loadV(kt, (kt & 1) ? vs1_u : vs0_u);
        CP_COMMIT();

        const float* Kb = (kt & 1) ? Ks1 : Ks0;

        // ---- S-mma(kt) ----
        float Sr[4][4], Si[4][4];
        #pragma unroll
        for (int i = 0; i < 4; i++) {
            Sr[i][0] = 0.f; Sr[i][1] = 0.f; Sr[i][2] = 0.f; Sr[i][3] = 0.f;
            Si[i][0] = 0.f; Si[i][1] = 0.f; Si[i][2] = 0.f; Si[i][3] = 0.f;
        }
        #pragma unroll 2
        for (int ks = 0; ks < 8; ks++) {
            const int col = 8 * ks + tg;
            const uint32_t ar0 = fu(qr[ks][0]), ar1 = fu(qr[ks][1]);
            const uint32_t ar2 = fu(qr[ks][2]), ar3 = fu(qr[ks][3]);
            const uint32_t ai0 = fu(qi[ks][0]), ai1 = fu(qi[ks][1]);
            const uint32_t ai2 = fu(qi[ks][2]), ai3 = fu(qi[ks][3]);
            const uint32_t nr0 = ar0 ^ 0x80000000u, nr1 = ar1 ^ 0x80000000u;
            const uint32_t nr2 = ar2 ^ 0x80000000u, nr3 = ar3 ^ 0x80000000u;
            #pragma unroll
            for (int nt = 0; nt < 4; nt++) {
                const float* kp = Kb + (8 * nt + g) * 132 + col;
                uint32_t br0 = fu(kp[0]);
                uint32_t br1 = fu(kp[4]);
                uint32_t bi0 = fu(kp[64]);
                uint32_t bi1 = fu(kp[68]);
                mma8(Sr[nt], ar0, ar1, ar2, ar3, br0, br1);  // qr.kr
                mma8(Sr[nt], ai0, ai1, ai2, ai3, bi0, bi1);  // + qi.ki
                mma8(Si[nt], ai0, ai1, ai2, ai3, br0, br1);  // qi.kr
                mma8(Si[nt], nr0, nr1, nr2, nr3, bi0, bi1);  // - qr.ki
            }
        }

        // ---- deferred PV(kt-1): no deps on this iteration's results ----
        if (kt > 0) doPV(kt - 1);

        // ---- softmax(kt): magnitude + exp via MUFU; store P(kt) ----
        float* Pw = (kt & 1) ? Ps1 : Ps0;
        #pragma unroll
        for (int nt = 0; nt < 4; nt++) {
            float h0 = fmaf(Si[nt][0], Si[nt][0], Sr[nt][0] * Sr[nt][0]);
            float h1 = fmaf(Si[nt][1], Si[nt][1], Sr[nt][1] * Sr[nt][1]);
            float h2 = fmaf(Si[nt][2], Si[nt][2], Sr[nt][2] * Sr[nt][2]);
            float h3 = fmaf(Si[nt][3], Si[nt][3], Sr[nt][3] * Sr[nt][3]);
            float p0 = ex2_ap(fmaf(sqrt_ap(h0), K1, K2));
            float p1 = ex2_ap(fmaf(sqrt_ap(h1), K1, K2));
            float p2 = ex2_ap(fmaf(sqrt_ap(h2), K1, K2));
            float p3 = ex2_ap(fmaf(sqrt_ap(h3), K1, K2));
            l0 += p0 + p1;
            l1 += p2 + p3;
            *(float2*)(Pw + (qrow + g) * 36 + 8 * nt + 2 * tg) = make_float2(tf32f(p0), tf32f(p1));
            *(float2*)(Pw + (qrow + g + 8) * 36 + 8 * nt + 2 * tg) = make_float2(tf32f(p2), tf32f(p3));
        }
        __syncwarp();   // each warp reads only its own 16 P rows next iter
    }

    // drain: PV(63). V(63) was issued at iter 63; ensure it landed + visible.
    CP_WAIT0();
    __syncthreads();
    doPV(63);

    // epilogue: divide by row sums, write tf32-rounded merged-head layout
    l0 += __shfl_xor_sync(0xffffffffu, l0, 1);
    l0 += __shfl_xor_sync(0xffffffffu, l0, 2);
    l1 += __shfl_xor_sync(0xffffffffu, l1, 1);
    l1 += __shfl_xor_sync(0xffffffffu, l1, 2);
    const float inv0 = 1.f / l0, inv1 = 1.f / l1;

    const int b_ = bh >> 4, hh = bh & 15;
    const int q = q0 + qrow + g;
    float* dst0 = g_z + (size_t)(b_ * 2048 + q) * 2048;
    float* dst1 = g_z + (size_t)(b_ * 2048 + q + 8) * 2048;
    #pragma unroll
    for (int nt = 0; nt < 16; nt++) {
        int d0 = 8 * nt + 2 * tg;
        int col = (d0 >> 6) * 1024 + hh * 64 + (d0 & 63);
        *(float2*)(dst0 + col) = make_float2(tf32f(O[nt][0] * inv0), tf32f(O[nt][1] * inv0));
        *(float2*)(dst1 + col) = make_float2(tf32f(O[nt][2] * inv1), tf32f(O[nt][3] * inv1));
    }
}

// ---------------------------------------------------------------------------
// Final GEMM: out[m][o] = sum_k g_z[m][k]*g_wc[o][k] + g_fb[o]
// M=4096, N=1024, K=2048. cp.async double-buffered.
// ---------------------------------------------------------------------------
__global__ void __launch_bounds__(256, 2) final_mma_kernel(float* __restrict__ Outp)
{
    extern __shared__ float sm[];
    float* As = sm;
    float* Bs = sm + 2 * 128 * 36;
    const uint32_t as_u = (uint32_t)__cvta_generic_to_shared(As);
    const uint32_t bs_u = (uint32_t)__cvta_generic_to_shared(Bs);

    const int t = threadIdx.x;
    const int w = t >> 5, lane = t & 31, g = lane >> 2, tg = lane & 3;
    const int wm = w >> 2, wn = w & 3;
    const int m0 = blockIdx.y * 128;
    const int o0 = blockIdx.x * 128;

    int lr[4], lc[4];
    #pragma unroll
    for (int i = 0; i < 4; i++) { int idx = i * 256 + t; lr[i] = idx >> 3; lc[i] = (idx & 7) * 4; }

    const float* Ag = g_z + (size_t)m0 * 2048;
    const float* Bg = g_wc + (size_t)o0 * 2048;

    auto loadAB = [&](int k0, int buf) {
        const int boff = buf * 128 * 36;
        #pragma unroll
        for (int i = 0; i < 4; i++) {
            cpa16(as_u + (boff + lr[i] * 36 + lc[i]) * 4, Ag + lr[i] * 2048 + k0 + lc[i]);
            cpa16(bs_u + (boff + lr[i] * 36 + lc[i]) * 4, Bg + lr[i] * 2048 + k0 + lc[i]);
        }
        CP_COMMIT();
    };

    float acc[4][4][4];
    #pragma unroll
    for (int a = 0; a < 4; a++)
        #pragma unroll
        for (int b = 0; b < 4; b++)
            #pragma unroll
            for (int c = 0; c < 4; c++) acc[a][b][c] = 0.f;

    loadAB(0, 0);

    for (int kt = 0; kt < 64; kt++) {
        CP_WAIT0();
        __syncthreads();
        if (kt + 1 < 64) loadAB((kt + 1) * 32, (kt + 1) & 1);
        const float* Ab = As + (kt & 1) * 128 * 36;
        const float* Bb = Bs + (kt & 1) * 128 * 36;
        #pragma unroll
        for (int ks = 0; ks < 4; ks++) {
            const int col = 8 * ks + tg;
            uint32_t a[4][4];
            #pragma unroll
            for (int mt = 0; mt < 4; mt++) {
                const float* ap = Ab + (64 * wm + 16 * mt + g) * 36;
                a[mt][0] = fu(ap[col]);
                a[mt][1] = fu(ap[8 * 36 + col]);
                a[mt][2] = fu(ap[col + 4]);
                a[mt][3] = fu(ap[8 * 36 + col + 4]);
            }
            #pragma unroll
            for (int nt = 0; nt < 4; nt++) {
                const float* bp = Bb + (32 * wn + 8 * nt + g) * 36;
                uint32_t b0 = fu(bp[col]);
                uint32_t b1 = fu(bp[col + 4]);
                #pragma unroll
                for (int mt = 0; mt < 4; mt++)
                    mma8(acc[mt][nt], a[mt][0], a[mt][1], a[mt][2], a[mt][3], b0, b1);
            }
        }
    }

    const int ob = o0 + 32 * wn;
    #pragma unroll
    for (int mt = 0; mt < 4; mt++) {
        int m = m0 + 64 * wm + 16 * mt + g;
        #pragma unroll
        for (int r = 0; r < 2; r++) {
            int mm = m + 8 * r;
            float* dst = Outp + (size_t)mm * 1024;
            #pragma unroll
            for (int nt = 0; nt < 4; nt++) {
                int o = ob + 8 * nt + 2 * tg;
                float2 fb = *(const float2*)(g_fb + o);
                *(float2*)(dst + o) =
                    make_float2(acc[mt][nt][2 * r + 0] + fb.x,
                                acc[mt][nt][2 * r + 1] + fb.y);
            }
        }
    }
}

// ---------------------------------------------------------------------------
extern "C" void kernel_launch(void* const* d_in, const int* in_sizes, int n_in,
                              void* d_out, int out_size)
{
    const float* x    = (const float*)d_in[0];
    const float* qr_w = (const float*)d_in[1];
    const float* qr_b = (const float*)d_in[2];
    const float* qi_w = (const float*)d_in[3];
    const float* qi_b = (const float*)d_in[4];
    const float* kr_w = (const float*)d_in[5];
    const float* kr_b = (const float*)d_in[6];
    const float* ki_w = (const float*)d_in[7];
    const float* ki_b = (const float*)d_in[8];
    const float* vr_w = (const float*)d_in[9];
    const float* vr_b = (const float*)d_in[10];
    const float* vi_w = (const float*)d_in[11];
    const float* vi_b = (const float*)d_in[12];
    const float* or_w = (const float*)d_in[13];
    const float* or_b = (const float*)d_in[14];
    const float* oi_w = (const float*)d_in[15];
    const float* oi_b = (const float*)d_in[16];
    float* out = (float*)d_out;

    static bool attr_set = false;
    if (!attr_set) {
        cudaFuncSetAttribute(proj_mma_kernel, cudaFuncAttributeMaxDynamicSharedMemorySize, PROJ_SMEM);
        cudaFuncSetAttribute(attn_mma_kernel, cudaFuncAttributeMaxDynamicSharedMemorySize, ATT_SMEM);
        cudaFuncSetAttribute(final_mma_kernel, cudaFuncAttributeMaxDynamicSharedMemorySize, PROJ_SMEM);
        attr_set = true;
    }

    prep_kernel<<<10240, 256>>>(x, qr_w, qi_w, kr_w, ki_w, vr_w, vi_w);
    make_wc_kernel<<<2048, 256>>>(or_w, oi_w, or_b, oi_b);

    proj_mma_kernel<<<dim3(16, 32, 3), 256, PROJ_SMEM>>>(
        qr_b, qi_b, kr_b, ki_b, vr_b, vi_b);

    attn_mma_kernel<<<dim3(32, 32), 128, ATT_SMEM>>>();

    final_mma_kernel<<<dim3(8, 32), 256, PROJ_SMEM>>>(out);
}

// round 12
// speedup vs baseline: 2.0545x; 2.0545x over previous
#include <cuda_runtime.h>
#include <cuda_fp16.h>
#include <cstdint>

// Problem: B=2, N=2048, C=1024, H=16, D=64 — fp16 storage, fp32 accumulate.
// g_q/g_k: half [bh=32][n=2048][128], d 0..63 real, 64..127 imag
// g_v:     half [bh=32][d=128][n=2048]   (d-major, written by proj)
// g_z:     half [b*2048+n][2048] = [out_r(1024) | out_i(1024)]
// g_x,g_w: half copies of x and the 6 QKV weights
// g_wc:    half combined output weight; g_fb: fp32 combined bias

#define PROJ_SMEM 73728   // 2 arrays x 2 bufs x 128 rows x 144 B
#define ATT_SMEM  43008   // K 2x8704 + V 2x10240 + P 5120

__device__ __half g_q[32 * 2048 * 128];
__device__ __half g_k[32 * 2048 * 128];
__device__ __half g_v[32 * 128 * 2048];
__device__ __half g_z[4096 * 2048];
__device__ __half g_x[4096 * 1024];
__device__ __half g_w[6 * 1024 * 1024];
__device__ __half g_wc[1024 * 2048];
__device__ float  g_fb[1024];

// ---------------------------------------------------------------------------
// helpers
// ---------------------------------------------------------------------------
__device__ __forceinline__ uint32_t h2pack(float lo, float hi) {
    uint32_t r;
    asm("cvt.rn.f16x2.f32 %0, %1, %2;" : "=r"(r) : "f"(hi), "f"(lo));
    return r;
}
__device__ __forceinline__ float sqrt_ap(float x) {
    float r; asm("sqrt.approx.f32 %0, %1;" : "=f"(r) : "f"(x)); return r;
}
__device__ __forceinline__ float ex2_ap(float x) {
    float r; asm("ex2.approx.f32 %0, %1;" : "=f"(r) : "f"(x)); return r;
}

// m16n8k16 fp16 mma, fp32 accumulate.
__device__ __forceinline__ void mma16(float* d,
                                      uint32_t a0, uint32_t a1, uint32_t a2, uint32_t a3,
                                      uint32_t b0, uint32_t b1) {
    asm volatile(
        "mma.sync.aligned.m16n8k16.row.col.f32.f16.f16.f32 "
        "{%0,%1,%2,%3}, {%4,%5,%6,%7}, {%8,%9}, {%0,%1,%2,%3};"
        : "+f"(d[0]), "+f"(d[1]), "+f"(d[2]), "+f"(d[3])
        : "r"(a0), "r"(a1), "r"(a2), "r"(a3), "r"(b0), "r"(b1));
}

__device__ __forceinline__ void cpa16(uint32_t dst, const void* src) {
    asm volatile("cp.async.cg.shared.global [%0], [%1], 16;" :: "r"(dst), "l"(src));
}
#define CP_COMMIT() asm volatile("cp.async.commit_group;")
#define CP_WAIT0()  asm volatile("cp.async.wait_group 0;")

// ---------------------------------------------------------------------------
// Convert x and the 6 QKV weights to fp16 (g_x / g_w).
// 2,621,440 float4 -> grid 10240 x 256.
// ---------------------------------------------------------------------------
__global__ void __launch_bounds__(256) prep_kernel(
    const float* __restrict__ x,
    const float* __restrict__ qrw, const float* __restrict__ qiw,
    const float* __restrict__ krw, const float* __restrict__ kiw,
    const float* __restrict__ vrw, const float* __restrict__ viw)
{
    int i4 = blockIdx.x * 256 + threadIdx.x;
    const float* src;
    __half* dst;
    if (i4 < 1048576) {
        src = x + (size_t)i4 * 4;
        dst = g_x + (size_t)i4 * 4;
    } else {
        int j = i4 - 1048576;
        int wsel = j >> 18;
        int off = j & 262143;
        const float* wp;
        switch (wsel) {
            case 0: wp = qrw; break;
            case 1: wp = qiw; break;
            case 2: wp = krw; break;
            case 3: wp = kiw; break;
            case 4: wp = vrw; break;
            default: wp = viw; break;
        }
        src = wp + (size_t)off * 4;
        dst = g_w + (size_t)wsel * 1048576 + (size_t)off * 4;
    }
    float4 v = *(const float4*)src;
    uint2 o;
    o.x = h2pack(v.x, v.y);
    o.y = h2pack(v.z, v.w);
    *(uint2*)dst = o;
}

// ---------------------------------------------------------------------------
// Combined output weight (fp16) + fp32 bias.
//   Wc[o][k<1024]  = or_w + 0.1*oi_w ;  Wc[o][k>=1024] = 0.1*or_w - oi_w
//   fb[o] = 1.1*or_b - 0.9*oi_b
// ---------------------------------------------------------------------------
__global__ void __launch_bounds__(256) make_wc_kernel(
    const float* __restrict__ orw, const float* __restrict__ oiw,
    const float* __restrict__ orb, const float* __restrict__ oib)
{
    int idx = blockIdx.x * 256 + threadIdx.x;
    int o = idx >> 9;
    int k = (idx & 511) << 2;
    float4 r;
    if (k < 1024) {
        float4 a = *(const float4*)(orw + (size_t)o * 1024 + k);
        float4 b = *(const float4*)(oiw + (size_t)o * 1024 + k);
        r.x = fmaf(0.1f, b.x, a.x); r.y = fmaf(0.1f, b.y, a.y);
        r.z = fmaf(0.1f, b.z, a.z); r.w = fmaf(0.1f, b.w, a.w);
    } else {
        int kk = k - 1024;
        float4 a = *(const float4*)(orw + (size_t)o * 1024 + kk);
        float4 b = *(const float4*)(oiw + (size_t)o * 1024 + kk);
        r.x = fmaf(0.1f, a.x, -b.x); r.y = fmaf(0.1f, a.y, -b.y);
        r.z = fmaf(0.1f, a.z, -b.z); r.w = fmaf(0.1f, a.w, -b.w);
    }
    uint2 ov;
    ov.x = h2pack(r.x, r.y);
    ov.y = h2pack(r.z, r.w);
    *(uint2*)(g_wc + (size_t)o * 2048 + k) = ov;
    if ((idx & 511) == 0)
        g_fb[o] = 1.1f * orb[o] - 0.9f * oib[o];
}

// ---------------------------------------------------------------------------
// Input projections: blockIdx.z = 0/1/2 -> Q/K/V.  fp16 m16n8k16 mma.
// BM=128, BN=128, BK=64 halves (128B/row), double-buffered cp.async.
// smem rows stride 36 half2-words (144B) -> conflict-free fragments.
// V output written d-major.
// ---------------------------------------------------------------------------
__global__ void __launch_bounds__(256, 2) proj_mma_kernel(
    const float* __restrict__ qrb, const float* __restrict__ qib,
    const float* __restrict__ krb, const float* __restrict__ kib,
    const float* __restrict__ vrb, const float* __restrict__ vib)
{
    extern __shared__ uint32_t smw[];
    const uint32_t smem_u = (uint32_t)__cvta_generic_to_shared(smw);

    const int t = threadIdx.x;
    const int w = t >> 5, lane = t & 31, g = lane >> 2, tg = lane & 3;
    const int wm = w >> 2, wn = w & 3;
    const int z = blockIdx.z;
    const int bx = blockIdx.x;
    const int m0 = blockIdx.y * 128;
    const bool imag = bx >= 8;
    const float* bias;
    __half* Out;
    if (z == 0)      { bias = imag ? qib : qrb; Out = g_q; }
    else if (z == 1) { bias = imag ? kib : krb; Out = g_k; }
    else             { bias = imag ? vib : vrb; Out = g_v; }
    const __half* W = g_w + (size_t)(z * 2 + (imag ? 1 : 0)) * 1024 * 1024;
    const int o0 = (bx & 7) * 128;

    const __half* Ag = g_x + (size_t)m0 * 1024;
    const __half* Bg = W + (size_t)o0 * 1024;

    // load one 128x64h tile of A and B into buffer `buf` (k0 in halves)
    auto loadAB = [&](int k0, int buf) {
        #pragma unroll
        for (int i = 0; i < 4; i++) {
            int idx = i * 256 + t;
            int row = idx >> 3, c = idx & 7;
            cpa16(smem_u + buf * 18432 + row * 144 + c * 16, Ag + row * 1024 + k0 + c * 8);
            cpa16(smem_u + 36864 + buf * 18432 + row * 144 + c * 16, Bg + row * 1024 + k0 + c * 8);
        }
        CP_COMMIT();
    };

    float acc[4][4][4];
    #pragma unroll
    for (int a = 0; a < 4; a++)
        #pragma unroll
        for (int b = 0; b < 4; b++)
            #pragma unroll
            for (int c = 0; c < 4; c++) acc[a][b][c] = 0.f;

    loadAB(0, 0);

    for (int kt = 0; kt < 16; kt++) {
        CP_WAIT0();
        __syncthreads();
        if (kt + 1 < 16) loadAB((kt + 1) * 64, (kt + 1) & 1);
        const uint32_t* Ab = smw + (kt & 1) * 4608;
        const uint32_t* Bb = smw + 9216 + (kt & 1) * 4608;
        #pragma unroll
        for (int ks = 0; ks < 4; ks++) {
            const int col = 8 * ks + tg;
            uint32_t a[4][4];
            #pragma unroll
            for (int mt = 0; mt < 4; mt++) {
                const uint32_t* ap = Ab + (64 * wm + 16 * mt + g) * 36;
                a[mt][0] = ap[col];
                a[mt][1] = ap[8 * 36 + col];
                a[mt][2] = ap[col + 4];
                a[mt][3] = ap[8 * 36 + col + 4];
            }
            #pragma unroll
            for (int nt = 0; nt < 4; nt++) {
                const uint32_t* bp = Bb + (32 * wn + 8 * nt + g) * 36;
                uint32_t b0 = bp[col];
                uint32_t b1 = bp[col + 4];
                #pragma unroll
                for (int mt = 0; mt < 4; mt++)
                    mma16(acc[mt][nt], a[mt][0], a[mt][1], a[mt][2], a[mt][3], b0, b1);
            }
        }
    }

    // epilogue
    const int part = imag ? 1 : 0;
    const int ob = o0 + 32 * wn;
    const int hh = ob >> 6;
    if (z == 2) {
        // V: d-major [bh][d][n]
        #pragma unroll
        for (int mt = 0; mt < 4; mt++) {
            int m = m0 + 64 * wm + 16 * mt + g;
            #pragma unroll
            for (int r = 0; r < 2; r++) {
                int mm = m + 8 * r;
                int b_ = mm >> 11, nn = mm & 2047;
                #pragma unroll
                for (int nt = 0; nt < 4; nt++) {
                    int o = ob + 8 * nt + 2 * tg;
                    float2 bv = *(const float2*)(bias + o);
                    size_t vrow = (size_t)(b_ * 16 + hh) * 128 + part * 64 + (o & 63);
                    g_v[vrow * 2048 + nn]       = __float2half_rn(acc[mt][nt][2 * r + 0] + bv.x);
                    g_v[(vrow + 1) * 2048 + nn] = __float2half_rn(acc[mt][nt][2 * r + 1] + bv.y);
                }
            }
        }
    } else {
        #pragma unroll
        for (int mt = 0; mt < 4; mt++) {
            int m = m0 + 64 * wm + 16 * mt + g;
            #pragma unroll
            for (int r = 0; r < 2; r++) {
                int mm = m + 8 * r;
                int b_ = mm >> 11, nn = mm & 2047;
                __half* dst = Out + ((size_t)(b_ * 16 + hh) * 2048 + nn) * 128 + part * 64;
                #pragma unroll
                for (int nt = 0; nt < 4; nt++) {
                    int o = ob + 8 * nt + 2 * tg;
                    float2 bv = *(const float2*)(bias + o);
                    *(uint32_t*)(dst + (o & 63)) =
                        h2pack(acc[mt][nt][2 * r + 0] + bv.x, acc[mt][nt][2 * r + 1] + bv.y);
                }
            }
        }
    }
}

// ---------------------------------------------------------------------------
// Fused complex-magnitude attention, fp16 m16n8k16 mma + MUFU softmax.
// Block = 64 queries x one bh; 4 warps; 32-key tiles; 3 CTAs/SM (43KB smem,
// regs capped 170 by launch_bounds(128,3)).
// Q fragments in registers (32 regs); K/V cp.async double-buffered.
// smem (half2 words): K stride 68, V (d-major) stride 20, P stride 20.
// Fixed-shift softmax: p = ex2(0.18034*|s| - 11.5416) == exp(0.125*|s| - 8).
// ---------------------------------------------------------------------------
__global__ void __launch_bounds__(128, 3) attn_mma_kernel()
{
    extern __shared__ uint32_t smw[];
    const uint32_t smem_u = (uint32_t)__cvta_generic_to_shared(smw);
    // word offsets: Ks0=0, Ks1=2176, Vs0=4352, Vs1=6912, P=9472
    const uint32_t ks0_u = smem_u;
    const uint32_t ks1_u = smem_u + 8704;
    const uint32_t vs0_u = smem_u + 17408;
    const uint32_t vs1_u = smem_u + 27648;
    uint32_t* Pw32 = smw + 9472;

    const int t = threadIdx.x;
    const int w = t >> 5, lane = t & 31, g = lane >> 2, tg = lane & 3;
    const int bh = blockIdx.y;
    const int q0 = blockIdx.x * 64;
    const int qrow = 16 * w;

    const __half* Qg = g_q + ((size_t)bh * 2048 + q0) * 128;
    const __half* Kg = g_k + (size_t)bh * 2048 * 128;
    const __half* Vg = g_v + (size_t)bh * 128 * 2048;

    // stage Q (64 rows x 256B, dst stride 272B) across the K double buffer
    #pragma unroll
    for (int i = 0; i < 8; i++) {
        int idx = i * 128 + t;
        int row = idx >> 4, c = idx & 15;
        cpa16(ks0_u + row * 272 + c * 16, Qg + row * 128 + c * 8);
    }
    CP_COMMIT();
    CP_WAIT0();
    __syncthreads();

    // Q fragments -> registers (half2 packed; 16 + 16 regs)
    uint32_t qr[4][4], qi[4][4];
    #pragma unroll
    for (int ks = 0; ks < 4; ks++) {
        const int col = 8 * ks + tg;
        const uint32_t* r0 = smw + (qrow + g) * 68;
        const uint32_t* r8 = smw + (qrow + g + 8) * 68;
        qr[ks][0] = r0[col];      qr[ks][1] = r8[col];
        qr[ks][2] = r0[col + 4];  qr[ks][3] = r8[col + 4];
        qi[ks][0] = r0[col + 32]; qi[ks][1] = r8[col + 32];
        qi[ks][2] = r0[col + 36]; qi[ks][3] = r8[col + 36];
    }
    __syncthreads();   // done reading staged Q before K(0) overwrites

    auto loadK = [&](int kt, uint32_t ku) {
        const __half* Kt = Kg + (size_t)kt * 32 * 128;
        #pragma unroll
        for (int i = 0; i < 4; i++) {
            int idx = i * 128 + t;
            int row = idx >> 4, c = idx & 15;
            cpa16(ku + row * 272 + c * 16, Kt + row * 128 + c * 8);
        }
    };
    auto loadV = [&](int kt, uint32_t vu) {
        #pragma unroll
        for (int i = 0; i < 4; i++) {
            int idx = i * 128 + t;
            int row = idx >> 2, c = idx & 3;
            cpa16(vu + row * 80 + c * 16, Vg + (size_t)row * 2048 + kt * 32 + c * 8);
        }
    };

    float O[16][4];
    #pragma unroll
    for (int i = 0; i < 16; i++) { O[i][0] = 0.f; O[i][1] = 0.f; O[i][2] = 0.f; O[i][3] = 0.f; }
    float l0 = 0.f, l1 = 0.f;

    const float K1 = 0.18033688f;   // 0.125 * log2(e)
    const float K2 = -11.541560f;   // -8 * log2(e)

    loadK(0, ks0_u);
    loadV(0, vs0_u);
    CP_COMMIT();

    for (int kt = 0; kt < 64; kt++) {
        CP_WAIT0();
        __syncthreads();
        if (kt + 1 < 64) {
            loadK(kt + 1, (kt & 1) ? ks0_u : ks1_u);
            loadV(kt + 1, (kt & 1) ? vs0_u : vs1_u);
            CP_COMMIT();
        }
        const uint32_t* Kb = smw + (kt & 1) * 2176;
        const uint32_t* Vb = smw + 4352 + (kt & 1) * 2560;

        float Sr[4][4], Si[4][4];
        #pragma unroll
        for (int i = 0; i < 4; i++) {
            Sr[i][0] = 0.f; Sr[i][1] = 0.f; Sr[i][2] = 0.f; Sr[i][3] = 0.f;
            Si[i][0] = 0.f; Si[i][1] = 0.f; Si[i][2] = 0.f; Si[i][3] = 0.f;
        }

        #pragma unroll
        for (int ks = 0; ks < 4; ks++) {
            const int col = 8 * ks + tg;
            const uint32_t ar0 = qr[ks][0], ar1 = qr[ks][1];
            const uint32_t ar2 = qr[ks][2], ar3 = qr[ks][3];
            const uint32_t ai0 = qi[ks][0], ai1 = qi[ks][1];
            const uint32_t ai2 = qi[ks][2], ai3 = qi[ks][3];
            const uint32_t nr0 = ar0 ^ 0x80008000u, nr1 = ar1 ^ 0x80008000u;
            const uint32_t nr2 = ar2 ^ 0x80008000u, nr3 = ar3 ^ 0x80008000u;
            #pragma unroll
            for (int nt = 0; nt < 4; nt++) {
                const uint32_t* kp = Kb + (8 * nt + g) * 68 + col;
                uint32_t br0 = kp[0];
                uint32_t br1 = kp[4];
                uint32_t bi0 = kp[32];
                uint32_t bi1 = kp[36];
                mma16(Sr[nt], ar0, ar1, ar2, ar3, br0, br1);  // qr.kr
                mma16(Sr[nt], ai0, ai1, ai2, ai3, bi0, bi1);  // + qi.ki
                mma16(Si[nt], ai0, ai1, ai2, ai3, br0, br1);  // qi.kr
                mma16(Si[nt], nr0, nr1, nr2, nr3, bi0, bi1);  // - qr.ki
            }
        }

        // magnitude + exp via MUFU; accumulate l; store P (fp16 pairs)
        #pragma unroll
        for (int nt = 0; nt < 4; nt++) {
            float h0 = fmaf(Si[nt][0], Si[nt][0], Sr[nt][0] * Sr[nt][0]);
            float h1 = fmaf(Si[nt][1], Si[nt][1], Sr[nt][1] * Sr[nt][1]);
            float h2 = fmaf(Si[nt][2], Si[nt][2], Sr[nt][2] * Sr[nt][2]);
            float h3 = fmaf(Si[nt][3], Si[nt][3], Sr[nt][3] * Sr[nt][3]);
            float p0 = ex2_ap(fmaf(sqrt_ap(h0), K1, K2));
            float p1 = ex2_ap(fmaf(sqrt_ap(h1), K1, K2));
            float p2 = ex2_ap(fmaf(sqrt_ap(h2), K1, K2));
            float p3 = ex2_ap(fmaf(sqrt_ap(h3), K1, K2));
            l0 += p0 + p1;
            l1 += p2 + p3;
            Pw32[(qrow + g) * 20 + 4 * nt + tg]     = h2pack(p0, p1);
            Pw32[(qrow + g + 8) * 20 + 4 * nt + tg] = h2pack(p2, p3);
        }
        __syncwarp();   // each warp reads only its own 16 P rows

        // O += P @ V   (V d-major: B rows = d, k = keys)
        #pragma unroll
        for (int kc = 0; kc < 2; kc++) {
            const int pcol = 8 * kc + tg;
            uint32_t a0 = Pw32[(qrow + g) * 20 + pcol];
            uint32_t a1 = Pw32[(qrow + g + 8) * 20 + pcol];
            uint32_t a2 = Pw32[(qrow + g) * 20 + pcol + 4];
            uint32_t a3 = Pw32[(qrow + g + 8) * 20 + pcol + 4];
            #pragma unroll
            for (int nt = 0; nt < 16; nt++) {
                const uint32_t* vp = Vb + (8 * nt + g) * 20 + pcol;
                mma16(O[nt], a0, a1, a2, a3, vp[0], vp[4]);
            }
        }
    }

    // epilogue: divide by row sums, write fp16 merged-head layout into g_z
    l0 += __shfl_xor_sync(0xffffffffu, l0, 1);
    l0 += __shfl_xor_sync(0xffffffffu, l0, 2);
    l1 += __shfl_xor_sync(0xffffffffu, l1, 1);
    l1 += __shfl_xor_sync(0xffffffffu, l1, 2);
    const float inv0 = 1.f / l0, inv1 = 1.f / l1;

    const int b_ = bh >> 4, hh = bh & 15;
    const int q = q0 + qrow + g;
    __half* dst0 = g_z + (size_t)(b_ * 2048 + q) * 2048;
    __half* dst1 = g_z + (size_t)(b_ * 2048 + q + 8) * 2048;
    #pragma unroll
    for (int nt = 0; nt < 16; nt++) {
        int d0 = 8 * nt + 2 * tg;
        int col = (d0 >> 6) * 1024 + hh * 64 + (d0 & 63);
        *(uint32_t*)(dst0 + col) = h2pack(O[nt][0] * inv0, O[nt][1] * inv0);
        *(uint32_t*)(dst1 + col) = h2pack(O[nt][2] * inv1, O[nt][3] * inv1);
    }
}

// ---------------------------------------------------------------------------
// Final GEMM: out[m][o] = sum_k g_z[m][k]*g_wc[o][k] + g_fb[o]
// M=4096, N=1024, K=2048 halves (32 ktiles of 64). fp32 output.
// ---------------------------------------------------------------------------
__global__ void __launch_bounds__(256, 2) final_mma_kernel(float* __restrict__ Outp)
{
    extern __shared__ uint32_t smw[];
    const uint32_t smem_u = (uint32_t)__cvta_generic_to_shared(smw);

    const int t = threadIdx.x;
    const int w = t >> 5, lane = t & 31, g = lane >> 2, tg = lane & 3;
    const int wm = w >> 2, wn = w & 3;
    const int m0 = blockIdx.y * 128;
    const int o0 = blockIdx.x * 128;

    const __half* Ag = g_z + (size_t)m0 * 2048;
    const __half* Bg = g_wc + (size_t)o0 * 2048;

    auto loadAB = [&](int k0, int buf) {
        #pragma unroll
        for (int i = 0; i < 4; i++) {
            int idx = i * 256 + t;
            int row = idx >> 3, c = idx & 7;
            cpa16(smem_u + buf * 18432 + row * 144 + c * 16, Ag + row * 2048 + k0 + c * 8);
            cpa16(smem_u + 36864 + buf * 18432 + row * 144 + c * 16, Bg + row * 2048 + k0 + c * 8);
        }
        CP_COMMIT();
    };

    float acc[4][4][4];
    #pragma unroll
    for (int a = 0; a < 4; a++)
        #pragma unroll
        for (int b = 0; b < 4; b++)
            #pragma unroll
            for (int c = 0; c < 4; c++) acc[a][b][c] = 0.f;

    loadAB(0, 0);

    for (int kt = 0; kt < 32; kt++) {
        CP_WAIT0();
        __syncthreads();
        if (kt + 1 < 32) loadAB((kt + 1) * 64, (kt + 1) & 1);
        const uint32_t* Ab = smw + (kt & 1) * 4608;
        const uint32_t* Bb = smw + 9216 + (kt & 1) * 4608;
        #pragma unroll
        for (int ks = 0; ks < 4; ks++) {
            const int col = 8 * ks + tg;
            uint32_t a[4][4];
            #pragma unroll
            for (int mt = 0; mt < 4; mt++) {
                const uint32_t* ap = Ab + (64 * wm + 16 * mt + g) * 36;
                a[mt][0] = ap[col];
                a[mt][1] = ap[8 * 36 + col];
                a[mt][2] = ap[col + 4];
                a[mt][3] = ap[8 * 36 + col + 4];
            }
            #pragma unroll
            for (int nt = 0; nt < 4; nt++) {
                const uint32_t* bp = Bb + (32 * wn + 8 * nt + g) * 36;
                uint32_t b0 = bp[col];
                uint32_t b1 = bp[col + 4];
                #pragma unroll
                for (int mt = 0; mt < 4; mt++)
                    mma16(acc[mt][nt], a[mt][0], a[mt][1], a[mt][2], a[mt][3], b0, b1);
            }
        }
    }

    const int ob = o0 + 32 * wn;
    #pragma unroll
    for (int mt = 0; mt < 4; mt++) {
        int m = m0 + 64 * wm + 16 * mt + g;
        #pragma unroll
        for (int r = 0; r < 2; r++) {
            int mm = m + 8 * r;
            float* dst = Outp + (size_t)mm * 1024;
            #pragma unroll
            for (int nt = 0; nt < 4; nt++) {
                int o = ob + 8 * nt + 2 * tg;
                float2 fb = *(const float2*)(g_fb + o);
                *(float2*)(dst + o) =
                    make_float2(acc[mt][nt][2 * r + 0] + fb.x,
                                acc[mt][nt][2 * r + 1] + fb.y);
            }
        }
    }
}

// ---------------------------------------------------------------------------
extern "C" void kernel_launch(void* const* d_in, const int* in_sizes, int n_in,
                              void* d_out, int out_size)
{
    const float* x    = (const float*)d_in[0];
    const float* qr_w = (const float*)d_in[1];
    const float* qr_b = (const float*)d_in[2];
    const float* qi_w = (const float*)d_in[3];
    const float* qi_b = (const float*)d_in[4];
    const float* kr_w = (const float*)d_in[5];
    const float* kr_b = (const float*)d_in[6];
    const float* ki_w = (const float*)d_in[7];
    const float* ki_b = (const float*)d_in[8];
    const float* vr_w = (const float*)d_in[9];
    const float* vr_b = (const float*)d_in[10];
    const float* vi_w = (const float*)d_in[11];
    const float* vi_b = (const float*)d_in[12];
    const float* or_w = (const float*)d_in[13];
    const float* or_b = (const float*)d_in[14];
    const float* oi_w = (const float*)d_in[15];
    const float* oi_b = (const float*)d_in[16];
    float* out = (float*)d_out;

    static bool attr_set = false;
    if (!attr_set) {
        cudaFuncSetAttribute(proj_mma_kernel, cudaFuncAttributeMaxDynamicSharedMemorySize, PROJ_SMEM);
        cudaFuncSetAttribute(attn_mma_kernel, cudaFuncAttributeMaxDynamicSharedMemorySize, ATT_SMEM);
        cudaFuncSetAttribute(final_mma_kernel, cudaFuncAttributeMaxDynamicSharedMemorySize, PROJ_SMEM);
        attr_set = true;
    }

    prep_kernel<<<10240, 256>>>(x, qr_w, qi_w, kr_w, ki_w, vr_w, vi_w);
    make_wc_kernel<<<2048, 256>>>(or_w, oi_w, or_b, oi_b);

    proj_mma_kernel<<<dim3(16, 32, 3), 256, PROJ_SMEM>>>(
        qr_b, qi_b, kr_b, ki_b, vr_b, vi_b);

    attn_mma_kernel<<<dim3(32, 32), 128, ATT_SMEM>>>();

    final_mma_kernel<<<dim3(8, 32), 256, PROJ_SMEM>>>(out);
}

// round 13
// speedup vs baseline: 2.1780x; 1.0601x over previous
#include <cuda_runtime.h>
#include <cuda_fp16.h>
#include <cstdint>

// Problem: B=2, N=2048, C=1024, H=16, D=64 — fp16 storage, fp32 accumulate.
// g_q/g_k: half [bh=32][n=2048][128], d 0..63 real, 64..127 imag
// g_v:     half [bh=32][d=128][n=2048]   (d-major, written by proj)
// g_z:     half [b*2048+n][2048] = [out_r(1024) | out_i(1024)]
// g_x,g_w: half copies of x and the 6 QKV weights
// g_wc:    half combined output weight; g_fb: fp32 combined bias

#define PROJ_SMEM 73728   // 2 arrays x 2 bufs x 128 rows x 144 B
#define ATT_SMEM  37888   // K 2x8704 + V 2x10240 (no P buffer)

__device__ __half g_q[32 * 2048 * 128];
__device__ __half g_k[32 * 2048 * 128];
__device__ __half g_v[32 * 128 * 2048];
__device__ __half g_z[4096 * 2048];
__device__ __half g_x[4096 * 1024];
__device__ __half g_w[6 * 1024 * 1024];
__device__ __half g_wc[1024 * 2048];
__device__ float  g_fb[1024];

// ---------------------------------------------------------------------------
// helpers
// ---------------------------------------------------------------------------
__device__ __forceinline__ uint32_t h2pack(float lo, float hi) {
    uint32_t r;
    asm("cvt.rn.f16x2.f32 %0, %1, %2;" : "=r"(r) : "f"(hi), "f"(lo));
    return r;
}
__device__ __forceinline__ float sqrt_ap(float x) {
    float r; asm("sqrt.approx.f32 %0, %1;" : "=f"(r) : "f"(x)); return r;
}
__device__ __forceinline__ float ex2_ap(float x) {
    float r; asm("ex2.approx.f32 %0, %1;" : "=f"(r) : "f"(x)); return r;
}

// m16n8k16 fp16 mma, fp32 accumulate.
__device__ __forceinline__ void mma16(float* d,
                                      uint32_t a0, uint32_t a1, uint32_t a2, uint32_t a3,
                                      uint32_t b0, uint32_t b1) {
    asm volatile(
        "mma.sync.aligned.m16n8k16.row.col.f32.f16.f16.f32 "
        "{%0,%1,%2,%3}, {%4,%5,%6,%7}, {%8,%9}, {%0,%1,%2,%3};"
        : "+f"(d[0]), "+f"(d[1]), "+f"(d[2]), "+f"(d[3])
        : "r"(a0), "r"(a1), "r"(a2), "r"(a3), "r"(b0), "r"(b1));
}

// ldmatrix x4: four 8x8 b16 tiles; lane l supplies the row address for
// tile (l>>3), row (l&7).
__device__ __forceinline__ void ldsm4(uint32_t& r0, uint32_t& r1,
                                      uint32_t& r2, uint32_t& r3, uint32_t addr) {
    asm volatile("ldmatrix.sync.aligned.m8n8.x4.shared.b16 {%0,%1,%2,%3}, [%4];"
                 : "=r"(r0), "=r"(r1), "=r"(r2), "=r"(r3) : "r"(addr));
}

__device__ __forceinline__ void cpa16(uint32_t dst, const void* src) {
    asm volatile("cp.async.cg.shared.global [%0], [%1], 16;" :: "r"(dst), "l"(src));
}
#define CP_COMMIT() asm volatile("cp.async.commit_group;")
#define CP_WAIT0()  asm volatile("cp.async.wait_group 0;")

// ---------------------------------------------------------------------------
// Convert x and the 6 QKV weights to fp16 (g_x / g_w).
// ---------------------------------------------------------------------------
__global__ void __launch_bounds__(256) prep_kernel(
    const float* __restrict__ x,
    const float* __restrict__ qrw, const float* __restrict__ qiw,
    const float* __restrict__ krw, const float* __restrict__ kiw,
    const float* __restrict__ vrw, const float* __restrict__ viw)
{
    int i4 = blockIdx.x * 256 + threadIdx.x;
    const float* src;
    __half* dst;
    if (i4 < 1048576) {
        src = x + (size_t)i4 * 4;
        dst = g_x + (size_t)i4 * 4;
    } else {
        int j = i4 - 1048576;
        int wsel = j >> 18;
        int off = j & 262143;
        const float* wp;
        switch (wsel) {
            case 0: wp = qrw; break;
            case 1: wp = qiw; break;
            case 2: wp = krw; break;
            case 3: wp = kiw; break;
            case 4: wp = vrw; break;
            default: wp = viw; break;
        }
        src = wp + (size_t)off * 4;
        dst = g_w + (size_t)wsel * 1048576 + (size_t)off * 4;
    }
    float4 v = *(const float4*)src;
    uint2 o;
    o.x = h2pack(v.x, v.y);
    o.y = h2pack(v.z, v.w);
    *(uint2*)dst = o;
}

// ---------------------------------------------------------------------------
// Combined output weight (fp16) + fp32 bias.
// ---------------------------------------------------------------------------
__global__ void __launch_bounds__(256) make_wc_kernel(
    const float* __restrict__ orw, const float* __restrict__ oiw,
    const float* __restrict__ orb, const float* __restrict__ oib)
{
    int idx = blockIdx.x * 256 + threadIdx.x;
    int o = idx >> 9;
    int k = (idx & 511) << 2;
    float4 r;
    if (k < 1024) {
        float4 a = *(const float4*)(orw + (size_t)o * 1024 + k);
        float4 b = *(const float4*)(oiw + (size_t)o * 1024 + k);
        r.x = fmaf(0.1f, b.x, a.x); r.y = fmaf(0.1f, b.y, a.y);
        r.z = fmaf(0.1f, b.z, a.z); r.w = fmaf(0.1f, b.w, a.w);
    } else {
        int kk = k - 1024;
        float4 a = *(const float4*)(orw + (size_t)o * 1024 + kk);
        float4 b = *(const float4*)(oiw + (size_t)o * 1024 + kk);
        r.x = fmaf(0.1f, a.x, -b.x); r.y = fmaf(0.1f, a.y, -b.y);
        r.z = fmaf(0.1f, a.z, -b.z); r.w = fmaf(0.1f, a.w, -b.w);
    }
    uint2 ov;
    ov.x = h2pack(r.x, r.y);
    ov.y = h2pack(r.z, r.w);
    *(uint2*)(g_wc + (size_t)o * 2048 + k) = ov;
    if ((idx & 511) == 0)
        g_fb[o] = 1.1f * orb[o] - 0.9f * oib[o];
}

// ---------------------------------------------------------------------------
// Input projections: blockIdx.z = 0/1/2 -> Q/K/V.  fp16 m16n8k16 mma.
// BM=128, BN=128, BK=64 halves, double-buffered cp.async.
// V output written d-major.
// ---------------------------------------------------------------------------
__global__ void __launch_bounds__(256, 2) proj_mma_kernel(
    const float* __restrict__ qrb, const float* __restrict__ qib,
    const float* __restrict__ krb, const float* __restrict__ kib,
    const float* __restrict__ vrb, const float* __restrict__ vib)
{
    extern __shared__ uint32_t smw[];
    const uint32_t smem_u = (uint32_t)__cvta_generic_to_shared(smw);

    const int t = threadIdx.x;
    const int w = t >> 5, lane = t & 31, g = lane >> 2, tg = lane & 3;
    const int wm = w >> 2, wn = w & 3;
    const int z = blockIdx.z;
    const int bx = blockIdx.x;
    const int m0 = blockIdx.y * 128;
    const bool imag = bx >= 8;
    const float* bias;
    __half* Out;
    if (z == 0)      { bias = imag ? qib : qrb; Out = g_q; }
    else if (z == 1) { bias = imag ? kib : krb; Out = g_k; }
    else             { bias = imag ? vib : vrb; Out = g_v; }
    const __half* W = g_w + (size_t)(z * 2 + (imag ? 1 : 0)) * 1024 * 1024;
    const int o0 = (bx & 7) * 128;

    const __half* Ag = g_x + (size_t)m0 * 1024;
    const __half* Bg = W + (size_t)o0 * 1024;

    auto loadAB = [&](int k0, int buf) {
        #pragma unroll
        for (int i = 0; i < 4; i++) {
            int idx = i * 256 + t;
            int row = idx >> 3, c = idx & 7;
            cpa16(smem_u + buf * 18432 + row * 144 + c * 16, Ag + row * 1024 + k0 + c * 8);
            cpa16(smem_u + 36864 + buf * 18432 + row * 144 + c * 16, Bg + row * 1024 + k0 + c * 8);
        }
        CP_COMMIT();
    };

    float acc[4][4][4];
    #pragma unroll
    for (int a = 0; a < 4; a++)
        #pragma unroll
        for (int b = 0; b < 4; b++)
            #pragma unroll
            for (int c = 0; c < 4; c++) acc[a][b][c] = 0.f;

    loadAB(0, 0);

    for (int kt = 0; kt < 16; kt++) {
        CP_WAIT0();
        __syncthreads();
        if (kt + 1 < 16) loadAB((kt + 1) * 64, (kt + 1) & 1);
        const uint32_t* Ab = smw + (kt & 1) * 4608;
        const uint32_t* Bb = smw + 9216 + (kt & 1) * 4608;
        #pragma unroll
        for (int ks = 0; ks < 4; ks++) {
            const int col = 8 * ks + tg;
            uint32_t a[4][4];
            #pragma unroll
            for (int mt = 0; mt < 4; mt++) {
                const uint32_t* ap = Ab + (64 * wm + 16 * mt + g) * 36;
                a[mt][0] = ap[col];
                a[mt][1] = ap[8 * 36 + col];
                a[mt][2] = ap[col + 4];
                a[mt][3] = ap[8 * 36 + col + 4];
            }
            #pragma unroll
            for (int nt = 0; nt < 4; nt++) {
                const uint32_t* bp = Bb + (32 * wn + 8 * nt + g) * 36;
                uint32_t b0 = bp[col];
                uint32_t b1 = bp[col + 4];
                #pragma unroll
                for (int mt = 0; mt < 4; mt++)
                    mma16(acc[mt][nt], a[mt][0], a[mt][1], a[mt][2], a[mt][3], b0, b1);
            }
        }
    }

    // epilogue
    const int part = imag ? 1 : 0;
    const int ob = o0 + 32 * wn;
    const int hh = ob >> 6;
    if (z == 2) {
        // V: d-major [bh][d][n]
        #pragma unroll
        for (int mt = 0; mt < 4; mt++) {
            int m = m0 + 64 * wm + 16 * mt + g;
            #pragma unroll
            for (int r = 0; r < 2; r++) {
                int mm = m + 8 * r;
                int b_ = mm >> 11, nn = mm & 2047;
                #pragma unroll
                for (int nt = 0; nt < 4; nt++) {
                    int o = ob + 8 * nt + 2 * tg;
                    float2 bv = *(const float2*)(bias + o);
                    size_t vrow = (size_t)(b_ * 16 + hh) * 128 + part * 64 + (o & 63);
                    g_v[vrow * 2048 + nn]       = __float2half_rn(acc[mt][nt][2 * r + 0] + bv.x);
                    g_v[(vrow + 1) * 2048 + nn] = __float2half_rn(acc[mt][nt][2 * r + 1] + bv.y);
                }
            }
        }
    } else {
        #pragma unroll
        for (int mt = 0; mt < 4; mt++) {
            int m = m0 + 64 * wm + 16 * mt + g;
            #pragma unroll
            for (int r = 0; r < 2; r++) {
                int mm = m + 8 * r;
                int b_ = mm >> 11, nn = mm & 2047;
                __half* dst = Out + ((size_t)(b_ * 16 + hh) * 2048 + nn) * 128 + part * 64;
                #pragma unroll
                for (int nt = 0; nt < 4; nt++) {
                    int o = ob + 8 * nt + 2 * tg;
                    float2 bv = *(const float2*)(bias + o);
                    *(uint32_t*)(dst + (o & 63)) =
                        h2pack(acc[mt][nt][2 * r + 0] + bv.x, acc[mt][nt][2 * r + 1] + bv.y);
                }
            }
        }
    }
}

// ---------------------------------------------------------------------------
// Fused complex-magnitude attention, fp16 m16n8k16 + ldmatrix + MUFU softmax.
// Block = 64 queries x one bh; 4 warps; 32-key tiles; 3 CTAs/SM (37KB smem).
// Q fragments in registers; P kept entirely in registers (the softmax output
// lanes coincide exactly with the PV A-fragment lanes -> no smem round-trip);
// K/V fragments loaded with ldmatrix.x4 (conflict-free rows).
// Fixed-shift softmax: p = ex2(0.18034*|s| - 11.5416) == exp(0.125*|s| - 8).
// ---------------------------------------------------------------------------
__global__ void __launch_bounds__(128, 3) attn_mma_kernel()
{
    extern __shared__ uint32_t smw[];
    const uint32_t smem_u = (uint32_t)__cvta_generic_to_shared(smw);
    // byte offsets: Ks0=0 (8704B), Ks1=8704, Vs0=17408 (10240B), Vs1=27648
    const uint32_t ks0_u = smem_u;
    const uint32_t ks1_u = smem_u + 8704;
    const uint32_t vs0_u = smem_u + 17408;
    const uint32_t vs1_u = smem_u + 27648;

    const int t = threadIdx.x;
    const int w = t >> 5, lane = t & 31, g = lane >> 2, tg = lane & 3;
    const int bh = blockIdx.y;
    const int q0 = blockIdx.x * 64;
    const int qrow = 16 * w;

    const __half* Qg = g_q + ((size_t)bh * 2048 + q0) * 128;
    const __half* Kg = g_k + (size_t)bh * 2048 * 128;
    const __half* Vg = g_v + (size_t)bh * 128 * 2048;

    // ldmatrix lane offsets (bytes)
    const int j = lane >> 3;                                  // tile index 0..3
    const uint32_t klane = (lane & 7) * 272 + (j & 1) * 16 + (j >> 1) * 128;
    const uint32_t vlane = (lane & 7) * 80 + j * 16;

    // stage Q (64 rows x 256B, dst stride 272B) across the K double buffer
    #pragma unroll
    for (int i = 0; i < 8; i++) {
        int idx = i * 128 + t;
        int row = idx >> 4, c = idx & 15;
        cpa16(ks0_u + row * 272 + c * 16, Qg + row * 128 + c * 8);
    }
    CP_COMMIT();
    CP_WAIT0();
    __syncthreads();

    // Q fragments -> registers (half2 packed; 16 + 16 regs)
    uint32_t qr[4][4], qi[4][4];
    #pragma unroll
    for (int ks = 0; ks < 4; ks++) {
        const int col = 8 * ks + tg;
        const uint32_t* r0 = smw + (qrow + g) * 68;
        const uint32_t* r8 = smw + (qrow + g + 8) * 68;
        qr[ks][0] = r0[col];      qr[ks][1] = r8[col];
        qr[ks][2] = r0[col + 4];  qr[ks][3] = r8[col + 4];
        qi[ks][0] = r0[col + 32]; qi[ks][1] = r8[col + 32];
        qi[ks][2] = r0[col + 36]; qi[ks][3] = r8[col + 36];
    }
    __syncthreads();   // done reading staged Q before K(0) overwrites

    auto loadK = [&](int kt, uint32_t ku) {
        const __half* Kt = Kg + (size_t)kt * 32 * 128;
        #pragma unroll
        for (int i = 0; i < 4; i++) {
            int idx = i * 128 + t;
            int row = idx >> 4, c = idx & 15;
            cpa16(ku + row * 272 + c * 16, Kt + row * 128 + c * 8);
        }
    };
    auto loadV = [&](int kt, uint32_t vu) {
        #pragma unroll
        for (int i = 0; i < 4; i++) {
            int idx = i * 128 + t;
            int row = idx >> 2, c = idx & 3;
            cpa16(vu + row * 80 + c * 16, Vg + (size_t)row * 2048 + kt * 32 + c * 8);
        }
    };

    float O[16][4];
    #pragma unroll
    for (int i = 0; i < 16; i++) { O[i][0] = 0.f; O[i][1] = 0.f; O[i][2] = 0.f; O[i][3] = 0.f; }
    float l0 = 0.f, l1 = 0.f;

    const float K1 = 0.18033688f;   // 0.125 * log2(e)
    const float K2 = -11.541560f;   // -8 * log2(e)

    loadK(0, ks0_u);
    loadV(0, vs0_u);
    CP_COMMIT();

    for (int kt = 0; kt < 64; kt++) {
        CP_WAIT0();
        __syncthreads();
        if (kt + 1 < 64) {
            loadK(kt + 1, (kt & 1) ? ks0_u : ks1_u);
            loadV(kt + 1, (kt & 1) ? vs0_u : vs1_u);
            CP_COMMIT();
        }
        const uint32_t kb_u = ((kt & 1) ? ks1_u : ks0_u) + klane;
        const uint32_t vb_u = ((kt & 1) ? vs1_u : vs0_u) + vlane;

        float Sr[4][4], Si[4][4];
        #pragma unroll
        for (int i = 0; i < 4; i++) {
            Sr[i][0] = 0.f; Sr[i][1] = 0.f; Sr[i][2] = 0.f; Sr[i][3] = 0.f;
            Si[i][0] = 0.f; Si[i][1] = 0.f; Si[i][2] = 0.f; Si[i][3] = 0.f;
        }

        #pragma unroll
        for (int ks = 0; ks < 4; ks++) {
            const uint32_t ar0 = qr[ks][0], ar1 = qr[ks][1];
            const uint32_t ar2 = qr[ks][2], ar3 = qr[ks][3];
            const uint32_t ai0 = qi[ks][0], ai1 = qi[ks][1];
            const uint32_t ai2 = qi[ks][2], ai3 = qi[ks][3];
            const uint32_t nr0 = ar0 ^ 0x80008000u, nr1 = ar1 ^ 0x80008000u;
            const uint32_t nr2 = ar2 ^ 0x80008000u, nr3 = ar3 ^ 0x80008000u;
            #pragma unroll
            for (int nt = 0; nt < 4; nt++) {
                uint32_t br0, br1, bi0, bi1;
                ldsm4(br0, br1, bi0, bi1, kb_u + nt * 2176 + ks * 32);
                mma16(Sr[nt], ar0, ar1, ar2, ar3, br0, br1);  // qr.kr
                mma16(Sr[nt], ai0, ai1, ai2, ai3, bi0, bi1);  // + qi.ki
                mma16(Si[nt], ai0, ai1, ai2, ai3, br0, br1);  // qi.kr
                mma16(Si[nt], nr0, nr1, nr2, nr3, bi0, bi1);  // - qr.ki
            }
        }

        // magnitude + exp via MUFU; accumulate l; P stays in registers:
        // pa[nt][0] = keys 8nt+2tg (rows qrow+g), pa[nt][1] = rows qrow+g+8.
        uint32_t pa[4][2];
        #pragma unroll
        for (int nt = 0; nt < 4; nt++) {
            float h0 = fmaf(Si[nt][0], Si[nt][0], Sr[nt][0] * Sr[nt][0]);
            float h1 = fmaf(Si[nt][1], Si[nt][1], Sr[nt][1] * Sr[nt][1]);
            float h2 = fmaf(Si[nt][2], Si[nt][2], Sr[nt][2] * Sr[nt][2]);
            float h3 = fmaf(Si[nt][3], Si[nt][3], Sr[nt][3] * Sr[nt][3]);
            float p0 = ex2_ap(fmaf(sqrt_ap(h0), K1, K2));
            float p1 = ex2_ap(fmaf(sqrt_ap(h1), K1, K2));
            float p2 = ex2_ap(fmaf(sqrt_ap(h2), K1, K2));
            float p3 = ex2_ap(fmaf(sqrt_ap(h3), K1, K2));
            l0 += p0 + p1;
            l1 += p2 + p3;
            pa[nt][0] = h2pack(p0, p1);
            pa[nt][1] = h2pack(p2, p3);
        }

        // O += P @ V  (A-fragment = pa in registers; V via ldmatrix:
        //  v0,v1 = keys 0..15 lo/hi, v2,v3 = keys 16..31 lo/hi)
        #pragma unroll
        for (int nt = 0; nt < 16; nt++) {
            uint32_t v0, v1, v2, v3;
            ldsm4(v0, v1, v2, v3, vb_u + nt * 640);
            mma16(O[nt], pa[0][0], pa[0][1], pa[1][0], pa[1][1], v0, v1);
            mma16(O[nt], pa[2][0], pa[2][1], pa[3][0], pa[3][1], v2, v3);
        }
    }

    // epilogue: divide by row sums, write fp16 merged-head layout into g_z
    l0 += __shfl_xor_sync(0xffffffffu, l0, 1);
    l0 += __shfl_xor_sync(0xffffffffu, l0, 2);
    l1 += __shfl_xor_sync(0xffffffffu, l1, 1);
    l1 += __shfl_xor_sync(0xffffffffu, l1, 2);
    const float inv0 = 1.f / l0, inv1 = 1.f / l1;

    const int b_ = bh >> 4, hh = bh & 15;
    const int q = q0 + qrow + g;
    __half* dst0 = g_z + (size_t)(b_ * 2048 + q) * 2048;
    __half* dst1 = g_z + (size_t)(b_ * 2048 + q + 8) * 2048;
    #pragma unroll
    for (int nt = 0; nt < 16; nt++) {
        int d0 = 8 * nt + 2 * tg;
        int col = (d0 >> 6) * 1024 + hh * 64 + (d0 & 63);
        *(uint32_t*)(dst0 + col) = h2pack(O[nt][0] * inv0, O[nt][1] * inv0);
        *(uint32_t*)(dst1 + col) = h2pack(O[nt][2] * inv1, O[nt][3] * inv1);
    }
}

// ---------------------------------------------------------------------------
// Final GEMM: out[m][o] = sum_k g_z[m][k]*g_wc[o][k] + g_fb[o]
// M=4096, N=1024, K=2048 halves (32 ktiles of 64). fp32 output.
// ---------------------------------------------------------------------------
__global__ void __launch_bounds__(256, 2) final_mma_kernel(float* __restrict__ Outp)
{
    extern __shared__ uint32_t smw[];
    const uint32_t smem_u = (uint32_t)__cvta_generic_to_shared(smw);

    const int t = threadIdx.x;
    const int w = t >> 5, lane = t & 31, g = lane >> 2, tg = lane & 3;
    const int wm = w >> 2, wn = w & 3;
    const int m0 = blockIdx.y * 128;
    const int o0 = blockIdx.x * 128;

    const __half* Ag = g_z + (size_t)m0 * 2048;
    const __half* Bg = g_wc + (size_t)o0 * 2048;

    auto loadAB = [&](int k0, int buf) {
        #pragma unroll
        for (int i = 0; i < 4; i++) {
            int idx = i * 256 + t;
            int row = idx >> 3, c = idx & 7;
            cpa16(smem_u + buf * 18432 + row * 144 + c * 16, Ag + row * 2048 + k0 + c * 8);
            cpa16(smem_u + 36864 + buf * 18432 + row * 144 + c * 16, Bg + row * 2048 + k0 + c * 8);
        }
        CP_COMMIT();
    };

    float acc[4][4][4];
    #pragma unroll
    for (int a = 0; a < 4; a++)
        #pragma unroll
        for (int b = 0; b < 4; b++)
            #pragma unroll
            for (int c = 0; c < 4; c++) acc[a][b][c] = 0.f;

    loadAB(0, 0);

    for (int kt = 0; kt < 32; kt++) {
        CP_WAIT0();
        __syncthreads();
        if (kt + 1 < 32) loadAB((kt + 1) * 64, (kt + 1) & 1);
        const uint32_t* Ab = smw + (kt & 1) * 4608;
        const uint32_t* Bb = smw + 9216 + (kt & 1) * 4608;
        #pragma unroll
        for (int ks = 0; ks < 4; ks++) {
            const int col = 8 * ks + tg;
            uint32_t a[4][4];
            #pragma unroll
            for (int mt = 0; mt < 4; mt++) {
                const uint32_t* ap = Ab + (64 * wm + 16 * mt + g) * 36;
                a[mt][0] = ap[col];
                a[mt][1] = ap[8 * 36 + col];
                a[mt][2] = ap[col + 4];
                a[mt][3] = ap[8 * 36 + col + 4];
            }
            #pragma unroll
            for (int nt = 0; nt < 4; nt++) {
                const uint32_t* bp = Bb + (32 * wn + 8 * nt + g) * 36;
                uint32_t b0 = bp[col];
                uint32_t b1 = bp[col + 4];
                #pragma unroll
                for (int mt = 0; mt < 4; mt++)
                    mma16(acc[mt][nt], a[mt][0], a[mt][1], a[mt][2], a[mt][3], b0, b1);
            }
        }
    }

    const int ob = o0 + 32 * wn;
    #pragma unroll
    for (int mt = 0; mt < 4; mt++) {
        int m = m0 + 64 * wm + 16 * mt + g;
        #pragma unroll
        for (int r = 0; r < 2; r++) {
            int mm = m + 8 * r;
            float* dst = Outp + (size_t)mm * 1024;
            #pragma unroll
            for (int nt = 0; nt < 4; nt++) {
                int o = ob + 8 * nt + 2 * tg;
                float2 fb = *(const float2*)(g_fb + o);
                *(float2*)(dst + o) =
                    make_float2(acc[mt][nt][2 * r + 0] + fb.x,
                                acc[mt][nt][2 * r + 1] + fb.y);
            }
        }
    }
}

// ---------------------------------------------------------------------------
extern "C" void kernel_launch(void* const* d_in, const int* in_sizes, int n_in,
                              void* d_out, int out_size)
{
    const float* x    = (const float*)d_in[0];
    const float* qr_w = (const float*)d_in[1];
    const float* qr_b = (const float*)d_in[2];
    const float* qi_w = (const float*)d_in[3];
    const float* qi_b = (const float*)d_in[4];
    const float* kr_w = (const float*)d_in[5];
    const float* kr_b = (const float*)d_in[6];
    const float* ki_w = (const float*)d_in[7];
    const float* ki_b = (const float*)d_in[8];
    const float* vr_w = (const float*)d_in[9];
    const float* vr_b = (const float*)d_in[10];
    const float* vi_w = (const float*)d_in[11];
    const float* vi_b = (const float*)d_in[12];
    const float* or_w = (const float*)d_in[13];
    const float* or_b = (const float*)d_in[14];
    const float* oi_w = (const float*)d_in[15];
    const float* oi_b = (const float*)d_in[16];
    float* out = (float*)d_out;

    static bool attr_set = false;
    if (!attr_set) {
        cudaFuncSetAttribute(proj_mma_kernel, cudaFuncAttributeMaxDynamicSharedMemorySize, PROJ_SMEM);
        cudaFuncSetAttribute(attn_mma_kernel, cudaFuncAttributeMaxDynamicSharedMemorySize, ATT_SMEM);
        cudaFuncSetAttribute(final_mma_kernel, cudaFuncAttributeMaxDynamicSharedMemorySize, PROJ_SMEM);
        attr_set = true;
    }

    prep_kernel<<<10240, 256>>>(x, qr_w, qi_w, kr_w, ki_w, vr_w, vi_w);
    make_wc_kernel<<<2048, 256>>>(or_w, oi_w, or_b, oi_b);

    proj_mma_kernel<<<dim3(16, 32, 3), 256, PROJ_SMEM>>>(
        qr_b, qi_b, kr_b, ki_b, vr_b, vi_b);

    attn_mma_kernel<<<dim3(32, 32), 128, ATT_SMEM>>>();

    final_mma_kernel<<<dim3(8, 32), 256, PROJ_SMEM>>>(out);
}

// round 15
// speedup vs baseline: 2.2912x; 1.0520x over previous
#include <cuda_runtime.h>
#include <cuda_fp16.h>
#include <cstdint>

// Problem: B=2, N=2048, C=1024, H=16, D=64 — fp16 storage, fp32 accumulate.
// g_q/g_k: half [bh=32][n=2048][128], d 0..63 real, 64..127 imag
// g_v:     half [bh=32][d=128][n=2048]   (d-major, written by proj)
// g_z:     half [b*2048+n][2048] = [out_r(1024) | out_i(1024)]
// g_x,g_w: half copies of x and the 6 QKV weights
// g_wc:    half combined output weight; g_fb: fp32 combined bias

#define PROJ_SMEM 73728   // 2 arrays x 2 bufs x 128 rows x 144 B
#define ATT_SMEM  37888   // K 2x8704 + V 2x10240

__device__ __half g_q[32 * 2048 * 128];
__device__ __half g_k[32 * 2048 * 128];
__device__ __half g_v[32 * 128 * 2048];
__device__ __half g_z[4096 * 2048];
__device__ __half g_x[4096 * 1024];
__device__ __half g_w[6 * 1024 * 1024];
__device__ __half g_wc[1024 * 2048];
__device__ float  g_fb[1024];

// ---------------------------------------------------------------------------
// helpers
// ---------------------------------------------------------------------------
__device__ __forceinline__ uint32_t h2pack(float lo, float hi) {
    uint32_t r;
    asm("cvt.rn.f16x2.f32 %0, %1, %2;" : "=r"(r) : "f"(hi), "f"(lo));
    return r;
}
__device__ __forceinline__ float sqrt_ap(float x) {
    float r; asm("sqrt.approx.f32 %0, %1;" : "=f"(r) : "f"(x)); return r;
}
__device__ __forceinline__ float ex2_ap(float x) {
    float r; asm("ex2.approx.f32 %0, %1;" : "=f"(r) : "f"(x)); return r;
}

// m16n8k16 fp16 mma, fp32 accumulate.
__device__ __forceinline__ void mma16(float* d,
                                      uint32_t a0, uint32_t a1, uint32_t a2, uint32_t a3,
                                      uint32_t b0, uint32_t b1) {
    asm volatile(
        "mma.sync.aligned.m16n8k16.row.col.f32.f16.f16.f32 "
        "{%0,%1,%2,%3}, {%4,%5,%6,%7}, {%8,%9}, {%0,%1,%2,%3};"
        : "+f"(d[0]), "+f"(d[1]), "+f"(d[2]), "+f"(d[3])
        : "r"(a0), "r"(a1), "r"(a2), "r"(a3), "r"(b0), "r"(b1));
}

// ldmatrix x4: four 8x8 b16 tiles; lane l supplies the row address for
// tile (l>>3), row (l&7).
__device__ __forceinline__ void ldsm4(uint32_t& r0, uint32_t& r1,
                                      uint32_t& r2, uint32_t& r3, uint32_t addr) {
    asm volatile("ldmatrix.sync.aligned.m8n8.x4.shared.b16 {%0,%1,%2,%3}, [%4];"
                 : "=r"(r0), "=r"(r1), "=r"(r2), "=r"(r3) : "r"(addr));
}

__device__ __forceinline__ void cpa16(uint32_t dst, const void* src) {
    asm volatile("cp.async.cg.shared.global [%0], [%1], 16;" :: "r"(dst), "l"(src));
}
#define CP_COMMIT() asm volatile("cp.async.commit_group;")
#define CP_WAIT0()  asm volatile("cp.async.wait_group 0;")

// ---------------------------------------------------------------------------
// Convert x and the 6 QKV weights to fp16 (g_x / g_w).
// ---------------------------------------------------------------------------
__global__ void __launch_bounds__(256) prep_kernel(
    const float* __restrict__ x,
    const float* __restrict__ qrw, const float* __restrict__ qiw,
    const float* __restrict__ krw, const float* __restrict__ kiw,
    const float* __restrict__ vrw, const float* __restrict__ viw)
{
    int i4 = blockIdx.x * 256 + threadIdx.x;
    const float* src;
    __half* dst;
    if (i4 < 1048576) {
        src = x + (size_t)i4 * 4;
        dst = g_x + (size_t)i4 * 4;
    } else {
        int j = i4 - 1048576;
        int wsel = j >> 18;
        int off = j & 262143;
        const float* wp;
        switch (wsel) {
            case 0: wp = qrw; break;
            case 1: wp = qiw; break;
            case 2: wp = krw; break;
            case 3: wp = kiw; break;
            case 4: wp = vrw; break;
            default: wp = viw; break;
        }
        src = wp + (size_t)off * 4;
        dst = g_w + (size_t)wsel * 1048576 + (size_t)off * 4;
    }
    float4 v = *(const float4*)src;
    uint2 o;
    o.x = h2pack(v.x, v.y);
    o.y = h2pack(v.z, v.w);
    *(uint2*)dst = o;
}

// ---------------------------------------------------------------------------
// Combined output weight (fp16) + fp32 bias.
// ---------------------------------------------------------------------------
__global__ void __launch_bounds__(256) make_wc_kernel(
    const float* __restrict__ orw, const float* __restrict__ oiw,
    const float* __restrict__ orb, const float* __restrict__ oib)
{
    int idx = blockIdx.x * 256 + threadIdx.x;
    int o = idx >> 9;
    int k = (idx & 511) << 2;
    float4 r;
    if (k < 1024) {
        float4 a = *(const float4*)(orw + (size_t)o * 1024 + k);
        float4 b = *(const float4*)(oiw + (size_t)o * 1024 + k);
        r.x = fmaf(0.1f, b.x, a.x); r.y = fmaf(0.1f, b.y, a.y);
        r.z = fmaf(0.1f, b.z, a.z); r.w = fmaf(0.1f, b.w, a.w);
    } else {
        int kk = k - 1024;
        float4 a = *(const float4*)(orw + (size_t)o * 1024 + kk);
        float4 b = *(const float4*)(oiw + (size_t)o * 1024 + kk);
        r.x = fmaf(0.1f, a.x, -b.x); r.y = fmaf(0.1f, a.y, -b.y);
        r.z = fmaf(0.1f, a.z, -b.z); r.w = fmaf(0.1f, a.w, -b.w);
    }
    uint2 ov;
    ov.x = h2pack(r.x, r.y);
    ov.y = h2pack(r.z, r.w);
    *(uint2*)(g_wc + (size_t)o * 2048 + k) = ov;
    if ((idx & 511) == 0)
        g_fb[o] = 1.1f * orb[o] - 0.9f * oib[o];
}

// ---------------------------------------------------------------------------
// Input projections: blockIdx.z = 0/1/2 -> Q/K/V.  fp16 m16n8k16 + ldmatrix.
// BM=128, BN=128, BK=64 halves, double-buffered cp.async.
// V output written d-major.
// ---------------------------------------------------------------------------
__global__ void __launch_bounds__(256, 2) proj_mma_kernel(
    const float* __restrict__ qrb, const float* __restrict__ qib,
    const float* __restrict__ krb, const float* __restrict__ kib,
    const float* __restrict__ vrb, const float* __restrict__ vib)
{
    extern __shared__ uint32_t smw[];
    const uint32_t smem_u = (uint32_t)__cvta_generic_to_shared(smw);

    const int t = threadIdx.x;
    const int w = t >> 5, lane = t & 31, g = lane >> 2, tg = lane & 3;
    const int wm = w >> 2, wn = w & 3;
    const int z = blockIdx.z;
    const int bx = blockIdx.x;
    const int m0 = blockIdx.y * 128;
    const bool imag = bx >= 8;
    const float* bias;
    __half* Out;
    if (z == 0)      { bias = imag ? qib : qrb; Out = g_q; }
    else if (z == 1) { bias = imag ? kib : krb; Out = g_k; }
    else             { bias = imag ? vib : vrb; Out = g_v; }
    const __half* W = g_w + (size_t)(z * 2 + (imag ? 1 : 0)) * 1024 * 1024;
    const int o0 = (bx & 7) * 128;

    const __half* Ag = g_x + (size_t)m0 * 1024;
    const __half* Bg = W + (size_t)o0 * 1024;

    // ldmatrix lane offsets (bytes), row stride 144 B
    const int j = lane >> 3;
    const uint32_t alane = ((j & 1) * 8 + (lane & 7)) * 144 + (j >> 1) * 16;
    const uint32_t blane = ((j >> 1) * 8 + (lane & 7)) * 144 + (j & 1) * 16;

    auto loadAB = [&](int k0, int buf) {
        #pragma unroll
        for (int i = 0; i < 4; i++) {
            int idx = i * 256 + t;
            int row = idx >> 3, c = idx & 7;
            cpa16(smem_u + buf * 18432 + row * 144 + c * 16, Ag + row * 1024 + k0 + c * 8);
            cpa16(smem_u + 36864 + buf * 18432 + row * 144 + c * 16, Bg + row * 1024 + k0 + c * 8);
        }
        CP_COMMIT();
    };

    float acc[4][4][4];
    #pragma unroll
    for (int a = 0; a < 4; a++)
        #pragma unroll
        for (int b = 0; b < 4; b++)
            #pragma unroll
            for (int c = 0; c < 4; c++) acc[a][b][c] = 0.f;

    loadAB(0, 0);

    for (int kt = 0; kt < 16; kt++) {
        CP_WAIT0();
        __syncthreads();
        if (kt + 1 < 16) loadAB((kt + 1) * 64, (kt + 1) & 1);
        const uint32_t ab_u = smem_u + (kt & 1) * 18432 + (64 * wm) * 144 + alane;
        const uint32_t bb_u = smem_u + 36864 + (kt & 1) * 18432 + (32 * wn) * 144 + blane;
        #pragma unroll
        for (int ks = 0; ks < 4; ks++) {
            uint32_t a[4][4];
            #pragma unroll
            for (int mt = 0; mt < 4; mt++)
                ldsm4(a[mt][0], a[mt][1], a[mt][2], a[mt][3],
                      ab_u + mt * (16 * 144) + ks * 32);
            #pragma unroll
            for (int np = 0; np < 2; np++) {
                uint32_t b0, b1, b2, b3;
                ldsm4(b0, b1, b2, b3, bb_u + np * (16 * 144) + ks * 32);
                #pragma unroll
                for (int mt = 0; mt < 4; mt++) {
                    mma16(acc[mt][2 * np],     a[mt][0], a[mt][1], a[mt][2], a[mt][3], b0, b1);
                    mma16(acc[mt][2 * np + 1], a[mt][0], a[mt][1], a[mt][2], a[mt][3], b2, b3);
                }
            }
        }
    }

    // epilogue
    const int part = imag ? 1 : 0;
    const int ob = o0 + 32 * wn;
    const int hh = ob >> 6;
    if (z == 2) {
        // V: d-major [bh][d][n]
        #pragma unroll
        for (int mt = 0; mt < 4; mt++) {
            int m = m0 + 64 * wm + 16 * mt + g;
            #pragma unroll
            for (int r = 0; r < 2; r++) {
                int mm = m + 8 * r;
                int b_ = mm >> 11, nn = mm & 2047;
                #pragma unroll
                for (int nt = 0; nt < 4; nt++) {
                    int o = ob + 8 * nt + 2 * tg;
                    float2 bv = *(const float2*)(bias + o);
                    size_t vrow = (size_t)(b_ * 16 + hh) * 128 + part * 64 + (o & 63);
                    g_v[vrow * 2048 + nn]       = __float2half_rn(acc[mt][nt][2 * r + 0] + bv.x);
                    g_v[(vrow + 1) * 2048 + nn] = __float2half_rn(acc[mt][nt][2 * r + 1] + bv.y);
                }
            }
        }
    } else {
        #pragma unroll
        for (int mt = 0; mt < 4; mt++) {
            int m = m0 + 64 * wm + 16 * mt + g;
            #pragma unroll
            for (int r = 0; r < 2; r++) {
                int mm = m + 8 * r;
                int b_ = mm >> 11, nn = mm & 2047;
                __half* dst = Out + ((size_t)(b_ * 16 + hh) * 2048 + nn) * 128 + part * 64;
                #pragma unroll
                for (int nt = 0; nt < 4; nt++) {
                    int o = ob + 8 * nt + 2 * tg;
                    float2 bv = *(const float2*)(bias + o);
                    *(uint32_t*)(dst + (o & 63)) =
                        h2pack(acc[mt][nt][2 * r + 0] + bv.x, acc[mt][nt][2 * r + 1] + bv.y);
                }
            }
        }
    }
}

// ---------------------------------------------------------------------------
// Fused complex-magnitude attention, fp16 m16n8k16 + ldmatrix + MUFU softmax.
// Block = 64 queries x one bh; 4 warps; 32-key tiles; 3 CTAs/SM.
// Q fragments in registers; P kept entirely in registers; K/V via ldmatrix.
// Fixed-shift softmax: p = ex2(0.18034*|s| - 11.5416) == exp(0.125*|s| - 8).
// ---------------------------------------------------------------------------
__global__ void __launch_bounds__(128, 3) attn_mma_kernel()
{
    extern __shared__ uint32_t smw[];
    const uint32_t smem_u = (uint32_t)__cvta_generic_to_shared(smw);
    const uint32_t ks0_u = smem_u;
    const uint32_t ks1_u = smem_u + 8704;
    const uint32_t vs0_u = smem_u + 17408;
    const uint32_t vs1_u = smem_u + 27648;

    const int t = threadIdx.x;
    const int w = t >> 5, lane = t & 31, g = lane >> 2, tg = lane & 3;
    const int bh = blockIdx.y;
    const int q0 = blockIdx.x * 64;
    const int qrow = 16 * w;

    const __half* Qg = g_q + ((size_t)bh * 2048 + q0) * 128;
    const __half* Kg = g_k + (size_t)bh * 2048 * 128;
    const __half* Vg = g_v + (size_t)bh * 128 * 2048;

    const int j = lane >> 3;
    const uint32_t klane = (lane & 7) * 272 + (j & 1) * 16 + (j >> 1) * 128;
    const uint32_t vlane = (lane & 7) * 80 + j * 16;

    // stage Q (64 rows x 256B, dst stride 272B) across the K double buffer
    #pragma unroll
    for (int i = 0; i < 8; i++) {
        int idx = i * 128 + t;
        int row = idx >> 4, c = idx & 15;
        cpa16(ks0_u + row * 272 + c * 16, Qg + row * 128 + c * 8);
    }
    CP_COMMIT();
    CP_WAIT0();
    __syncthreads();

    // Q fragments -> registers (half2 packed)
    uint32_t qr[4][4], qi[4][4];
    #pragma unroll
    for (int ks = 0; ks < 4; ks++) {
        const int col = 8 * ks + tg;
        const uint32_t* r0 = smw + (qrow + g) * 68;
        const uint32_t* r8 = smw + (qrow + g + 8) * 68;
        qr[ks][0] = r0[col];      qr[ks][1] = r8[col];
        qr[ks][2] = r0[col + 4];  qr[ks][3] = r8[col + 4];
        qi[ks][0] = r0[col + 32]; qi[ks][1] = r8[col + 32];
        qi[ks][2] = r0[col + 36]; qi[ks][3] = r8[col + 36];
    }
    __syncthreads();   // done reading staged Q before K(0) overwrites

    auto loadK = [&](int kt, uint32_t ku) {
        const __half* Kt = Kg + (size_t)kt * 32 * 128;
        #pragma unroll
        for (int i = 0; i < 4; i++) {
            int idx = i * 128 + t;
            int row = idx >> 4, c = idx & 15;
            cpa16(ku + row * 272 + c * 16, Kt + row * 128 + c * 8);
        }
    };
    auto loadV = [&](int kt, uint32_t vu) {
        #pragma unroll
        for (int i = 0; i < 4; i++) {
            int idx = i * 128 + t;
            int row = idx >> 2, c = idx & 3;
            cpa16(vu + row * 80 + c * 16, Vg + (size_t)row * 2048 + kt * 32 + c * 8);
        }
    };

    float O[16][4];
    #pragma unroll
    for (int i = 0; i < 16; i++) { O[i][0] = 0.f; O[i][1] = 0.f; O[i][2] = 0.f; O[i][3] = 0.f; }
    float l0 = 0.f, l1 = 0.f;

    const float K1 = 0.18033688f;   // 0.125 * log2(e)
    const float K2 = -11.541560f;   // -8 * log2(e)

    loadK(0, ks0_u);
    loadV(0, vs0_u);
    CP_COMMIT();

    for (int kt = 0; kt < 64; kt++) {
        CP_WAIT0();
        __syncthreads();
        if (kt + 1 < 64) {
            loadK(kt + 1, (kt & 1) ? ks0_u : ks1_u);
            loadV(kt + 1, (kt & 1) ? vs0_u : vs1_u);
            CP_COMMIT();
        }
        const uint32_t kb_u = ((kt & 1) ? ks1_u : ks0_u) + klane;
        const uint32_t vb_u = ((kt & 1) ? vs1_u : vs0_u) + vlane;

        float Sr[4][4], Si[4][4];
        #pragma unroll
        for (int i = 0; i < 4; i++) {
            Sr[i][0] = 0.f; Sr[i][1] = 0.f; Sr[i][2] = 0.f; Sr[i][3] = 0.f;
            Si[i][0] = 0.f; Si[i][1] = 0.f; Si[i][2] = 0.f; Si[i][3] = 0.f;
        }

        #pragma unroll
        for (int ks = 0; ks < 4; ks++) {
            const uint32_t ar0 = qr[ks][0], ar1 = qr[ks][1];
            const uint32_t ar2 = qr[ks][2], ar3 = qr[ks][3];
            const uint32_t ai0 = qi[ks][0], ai1 = qi[ks][1];
            const uint32_t ai2 = qi[ks][2], ai3 = qi[ks][3];
            const uint32_t nr0 = ar0 ^ 0x80008000u, nr1 = ar1 ^ 0x80008000u;
            const uint32_t nr2 = ar2 ^ 0x80008000u, nr3 = ar3 ^ 0x80008000u;
            #pragma unroll
            for (int nt = 0; nt < 4; nt++) {
                uint32_t br0, br1, bi0, bi1;
                ldsm4(br0, br1, bi0, bi1, kb_u + nt * 2176 + ks * 32);
                mma16(Sr[nt], ar0, ar1, ar2, ar3, br0, br1);  // qr.kr
                mma16(Sr[nt], ai0, ai1, ai2, ai3, bi0, bi1);  // + qi.ki
                mma16(Si[nt], ai0, ai1, ai2, ai3, br0, br1);  // qi.kr
                mma16(Si[nt], nr0, nr1, nr2, nr3, bi0, bi1);  // - qr.ki
            }
        }

        // magnitude + exp via MUFU; accumulate l; P in registers
        uint32_t pa[4][2];
        #pragma unroll
        for (int nt = 0; nt < 4; nt++) {
            float h0 = fmaf(Si[nt][0], Si[nt][0], Sr[nt][0] * Sr[nt][0]);
            float h1 = fmaf(Si[nt][1], Si[nt][1], Sr[nt][1] * Sr[nt][1]);
            float h2 = fmaf(Si[nt][2], Si[nt][2], Sr[nt][2] * Sr[nt][2]);
            float h3 = fmaf(Si[nt][3], Si[nt][3], Sr[nt][3] * Sr[nt][3]);
            float p0 = ex2_ap(fmaf(sqrt_ap(h0), K1, K2));
            float p1 = ex2_ap(fmaf(sqrt_ap(h1), K1, K2));
            float p2 = ex2_ap(fmaf(sqrt_ap(h2), K1, K2));
            float p3 = ex2_ap(fmaf(sqrt_ap(h3), K1, K2));
            l0 += p0 + p1;
            l1 += p2 + p3;
            pa[nt][0] = h2pack(p0, p1);
            pa[nt][1] = h2pack(p2, p3);
        }

        // O += P @ V  (A = pa in registers; V via ldmatrix)
        #pragma unroll
        for (int nt = 0; nt < 16; nt++) {
            uint32_t v0, v1, v2, v3;
            ldsm4(v0, v1, v2, v3, vb_u + nt * 640);
            mma16(O[nt], pa[0][0], pa[0][1], pa[1][0], pa[1][1], v0, v1);
            mma16(O[nt], pa[2][0], pa[2][1], pa[3][0], pa[3][1], v2, v3);
        }
    }

    // epilogue: divide by row sums, write fp16 merged-head layout into g_z
    l0 += __shfl_xor_sync(0xffffffffu, l0, 1);
    l0 += __shfl_xor_sync(0xffffffffu, l0, 2);
    l1 += __shfl_xor_sync(0xffffffffu, l1, 1);
    l1 += __shfl_xor_sync(0xffffffffu, l1, 2);
    const float inv0 = 1.f / l0, inv1 = 1.f / l1;

    const int b_ = bh >> 4, hh = bh & 15;
    const int q = q0 + qrow + g;
    __half* dst0 = g_z + (size_t)(b_ * 2048 + q) * 2048;
    __half* dst1 = g_z + (size_t)(b_ * 2048 + q + 8) * 2048;
    #pragma unroll
    for (int nt = 0; nt < 16; nt++) {
        int d0 = 8 * nt + 2 * tg;
        int col = (d0 >> 6) * 1024 + hh * 64 + (d0 & 63);
        *(uint32_t*)(dst0 + col) = h2pack(O[nt][0] * inv0, O[nt][1] * inv0);
        *(uint32_t*)(dst1 + col) = h2pack(O[nt][2] * inv1, O[nt][3] * inv1);
    }
}

// ---------------------------------------------------------------------------
// Final GEMM: out[m][o] = sum_k g_z[m][k]*g_wc[o][k] + g_fb[o]
// M=4096, N=1024, K=2048 halves (32 ktiles of 64). ldmatrix fragments.
// ---------------------------------------------------------------------------
__global__ void __launch_bounds__(256, 2) final_mma_kernel(float* __restrict__ Outp)
{
    extern __shared__ uint32_t smw[];
    const uint32_t smem_u = (uint32_t)__cvta_generic_to_shared(smw);

    const int t = threadIdx.x;
    const int w = t >> 5, lane = t & 31, g = lane >> 2, tg = lane & 3;
    const int wm = w >> 2, wn = w & 3;
    const int m0 = blockIdx.y * 128;
    const int o0 = blockIdx.x * 128;

    const __half* Ag = g_z + (size_t)m0 * 2048;
    const __half* Bg = g_wc + (size_t)o0 * 2048;

    const int j = lane >> 3;
    const uint32_t alane = ((j & 1) * 8 + (lane & 7)) * 144 + (j >> 1) * 16;
    const uint32_t blane = ((j >> 1) * 8 + (lane & 7)) * 144 + (j & 1) * 16;

    auto loadAB = [&](int k0, int buf) {
        #pragma unroll
        for (int i = 0; i < 4; i++) {
            int idx = i * 256 + t;
            int row = idx >> 3, c = idx & 7;
            cpa16(smem_u + buf * 18432 + row * 144 + c * 16, Ag + row * 2048 + k0 + c * 8);
            cpa16(smem_u + 36864 + buf * 18432 + row * 144 + c * 16, Bg + row * 2048 + k0 + c * 8);
        }
        CP_COMMIT();
    };

    float acc[4][4][4];
    #pragma unroll
    for (int a = 0; a < 4; a++)
        #pragma unroll
        for (int b = 0; b < 4; b++)
            #pragma unroll
            for (int c = 0; c < 4; c++) acc[a][b][c] = 0.f;

    loadAB(0, 0);

    for (int kt = 0; kt < 32; kt++) {
        CP_WAIT0();
        __syncthreads();
        if (kt + 1 < 32) loadAB((kt + 1) * 64, (kt + 1) & 1);
        const uint32_t ab_u = smem_u + (kt & 1) * 18432 + (64 * wm) * 144 + alane;
        const uint32_t bb_u = smem_u + 36864 + (kt & 1) * 18432 + (32 * wn) * 144 + blane;
        #pragma unroll
        for (int ks = 0; ks < 4; ks++) {
            uint32_t a[4][4];
            #pragma unroll
            for (int mt = 0; mt < 4; mt++)
                ldsm4(a[mt][0], a[mt][1], a[mt][2], a[mt][3],
                      ab_u + mt * (16 * 144) + ks * 32);
            #pragma unroll
            for (int np = 0; np < 2; np++) {
                uint32_t b0, b1, b2, b3;
                ldsm4(b0, b1, b2, b3, bb_u + np * (16 * 144) + ks * 32);
                #pragma unroll
                for (int mt = 0; mt < 4; mt++) {
                    mma16(acc[mt][2 * np],     a[mt][0], a[mt][1], a[mt][2], a[mt][3], b0, b1);
                    mma16(acc[mt][2 * np + 1], a[mt][0], a[mt][1], a[mt][2], a[mt][3], b2, b3);
                }
            }
        }
    }

    const int ob = o0 + 32 * wn;
    #pragma unroll
    for (int mt = 0; mt < 4; mt++) {
        int m = m0 + 64 * wm + 16 * mt + g;
        #pragma unroll
        for (int r = 0; r < 2; r++) {
            int mm = m + 8 * r;
            float* dst = Outp + (size_t)mm * 1024;
            #pragma unroll
            for (int nt = 0; nt < 4; nt++) {
                int o = ob + 8 * nt + 2 * tg;
                float2 fb = *(const float2*)(g_fb + o);
                *(float2*)(dst + o) =
                    make_float2(acc[mt][nt][2 * r + 0] + fb.x,
                                acc[mt][nt][2 * r + 1] + fb.y);
            }
        }
    }
}

// ---------------------------------------------------------------------------
extern "C" void kernel_launch(void* const* d_in, const int* in_sizes, int n_in,
                              void* d_out, int out_size)
{
    const float* x    = (const float*)d_in[0];
    const float* qr_w = (const float*)d_in[1];
    const float* qr_b = (const float*)d_in[2];
    const float* qi_w = (const float*)d_in[3];
    const float* qi_b = (const float*)d_in[4];
    const float* kr_w = (const float*)d_in[5];
    const float* kr_b = (const float*)d_in[6];
    const float* ki_w = (const float*)d_in[7];
    const float* ki_b = (const float*)d_in[8];
    const float* vr_w = (const float*)d_in[9];
    const float* vr_b = (const float*)d_in[10];
    const float* vi_w = (const float*)d_in[11];
    const float* vi_b = (const float*)d_in[12];
    const float* or_w = (const float*)d_in[13];
    const float* or_b = (const float*)d_in[14];
    const float* oi_w = (const float*)d_in[15];
    const float* oi_b = (const float*)d_in[16];
    float* out = (float*)d_out;

    static bool attr_set = false;
    if (!attr_set) {
        cudaFuncSetAttribute(proj_mma_kernel, cudaFuncAttributeMaxDynamicSharedMemorySize, PROJ_SMEM);
        cudaFuncSetAttribute(attn_mma_kernel, cudaFuncAttributeMaxDynamicSharedMemorySize, ATT_SMEM);
        cudaFuncSetAttribute(final_mma_kernel, cudaFuncAttributeMaxDynamicSharedMemorySize, PROJ_SMEM);
        attr_set = true;
    }

    prep_kernel<<<10240, 256>>>(x, qr_w, qi_w, kr_w, ki_w, vr_w, vi_w);
    make_wc_kernel<<<2048, 256>>>(or_w, oi_w, or_b, oi_b);

    proj_mma_kernel<<<dim3(16, 32, 3), 256, PROJ_SMEM>>>(
        qr_b, qi_b, kr_b, ki_b, vr_b, vi_b);

    attn_mma_kernel<<<dim3(32, 32), 128, ATT_SMEM>>>();

    final_mma_kernel<<<dim3(8, 32), 256, PROJ_SMEM>>>(out);
}